// round 12
// baseline (speedup 1.0000x reference)
#include <cuda_runtime.h>
#include <cuda_fp16.h>
#include <math.h>

#define NU 200000
#define NB 50000
#define NE 5000000
#define STRIDE_B 192
#define STRIDE_U 64

// ---------------- scratch ----------------
__device__ int g_cnt[NU + NB];
__device__ int g_bkt_ub[(size_t)NB * STRIDE_B];
__device__ int g_bkt_bu[(size_t)NU * STRIDE_U];
__device__ unsigned short g_rank_ub[NE];
__device__ unsigned short g_rank_bu[NE];

__device__ uint4 g_hs1_u[NU * 2];         // fp16 rows: 16 halves = 32B
__device__ uint4 g_hs1_b[NB * 2];
__device__ float g_ad1_u[NU];
__device__ float g_ad1_b[NB];
__device__ float g_hs2_u[NU * 2], g_hs2_b[NB * 2];
__device__ float g_ad2_u[NU];
__device__ float g_ad2_b[NB];

#define GE8_BLOCKS ((NE / 8 + 255) / 256)
#define UBLK ((NU + 255) / 256)
#define BBLK ((NB + 255) / 256)

// ---------------- Kernel A: count (+rank record, coalesced) + node transform ----------
// Atomic returns are stored as packed ushort ranks (coalesced uint4 store) —
// no scattered store depends on the 318-cyc atomic return. Low regs -> high occ.
__global__ void count_node_kernel(
    const int* __restrict__ ub_dst, int* __restrict__ cnt_ub,
    unsigned short* __restrict__ rank_ub,
    const int* __restrict__ bu_dst, int* __restrict__ cnt_bu,
    unsigned short* __restrict__ rank_bu,
    const float* __restrict__ xu, const float* __restrict__ xb,
    const float* __restrict__ Ws_u, const float* __restrict__ Wd_u,
    const float* __restrict__ avd_u,
    const float* __restrict__ Ws_b, const float* __restrict__ Wd_b,
    const float* __restrict__ avd_b,
    uint4* __restrict__ hs_u, float* __restrict__ ad_u,
    uint4* __restrict__ hs_b, float* __restrict__ ad_b) {
    __shared__ float sWs[64 * 16], swd[64];

    if (blockIdx.x < GE8_BLOCKS) {
        int t = blockIdx.x * 256 + threadIdx.x;
        if (t >= NE / 8) return;
        int4 da0 = ((const int4*)ub_dst)[2 * t + 0];
        int4 da1 = ((const int4*)ub_dst)[2 * t + 1];
        int4 db0 = ((const int4*)bu_dst)[2 * t + 0];
        int4 db1 = ((const int4*)bu_dst)[2 * t + 1];

        unsigned int r0 = atomicAdd(&cnt_ub[da0.x], 1);
        unsigned int r1 = atomicAdd(&cnt_ub[da0.y], 1);
        unsigned int r2 = atomicAdd(&cnt_ub[da0.z], 1);
        unsigned int r3 = atomicAdd(&cnt_ub[da0.w], 1);
        unsigned int r4 = atomicAdd(&cnt_ub[da1.x], 1);
        unsigned int r5 = atomicAdd(&cnt_ub[da1.y], 1);
        unsigned int r6 = atomicAdd(&cnt_ub[da1.z], 1);
        unsigned int r7 = atomicAdd(&cnt_ub[da1.w], 1);
        unsigned int q0 = atomicAdd(&cnt_bu[db0.x], 1);
        unsigned int q1 = atomicAdd(&cnt_bu[db0.y], 1);
        unsigned int q2 = atomicAdd(&cnt_bu[db0.z], 1);
        unsigned int q3 = atomicAdd(&cnt_bu[db0.w], 1);
        unsigned int q4 = atomicAdd(&cnt_bu[db1.x], 1);
        unsigned int q5 = atomicAdd(&cnt_bu[db1.y], 1);
        unsigned int q6 = atomicAdd(&cnt_bu[db1.z], 1);
        unsigned int q7 = atomicAdd(&cnt_bu[db1.w], 1);

        uint4 pa, pb;
        pa.x = (r0 & 0xffffu) | (r1 << 16);
        pa.y = (r2 & 0xffffu) | (r3 << 16);
        pa.z = (r4 & 0xffffu) | (r5 << 16);
        pa.w = (r6 & 0xffffu) | (r7 << 16);
        pb.x = (q0 & 0xffffu) | (q1 << 16);
        pb.y = (q2 & 0xffffu) | (q3 << 16);
        pb.z = (q4 & 0xffffu) | (q5 << 16);
        pb.w = (q6 & 0xffffu) | (q7 << 16);
        ((uint4*)rank_ub)[t] = pa;
        ((uint4*)rank_bu)[t] = pb;
        return;
    }

    // ---------- node transform (ad = x @ (Wd @ avd)) ----------
    int nb = blockIdx.x - GE8_BLOCKS;
    bool isU = (nb < UBLK);
    const float* x   = isU ? xu : xb;
    const float* Ws  = isU ? Ws_u : Ws_b;
    const float* Wd  = isU ? Wd_u : Wd_b;
    const float* avd = isU ? avd_u : avd_b;
    uint4* hso       = isU ? hs_u : hs_b;
    float* ado       = isU ? ad_u : ad_b;
    int n            = isU ? NU : NB;
    int i = (isU ? nb : nb - UBLK) * 256 + threadIdx.x;

    for (int j = threadIdx.x; j < 1024; j += 256) sWs[j] = Ws[j];
    if (threadIdx.x < 64) {
        float acc = 0.f;
#pragma unroll
        for (int c = 0; c < 16; c++) acc += Wd[threadIdx.x * 16 + c] * avd[c];
        swd[threadIdx.x] = acc;
    }
    __syncthreads();
    if (i >= n) return;

    float hs[16];
#pragma unroll
    for (int c = 0; c < 16; c++) hs[c] = 0.f;
    float ad = 0.f;
    const float4* xp = (const float4*)(x + (size_t)i * 64);
#pragma unroll 4
    for (int q = 0; q < 16; q++) {
        float4 v = xp[q];
#pragma unroll
        for (int kk = 0; kk < 4; kk++) {
            float xk = (kk == 0) ? v.x : (kk == 1) ? v.y : (kk == 2) ? v.z : v.w;
            int k = q * 4 + kk;
#pragma unroll
            for (int c = 0; c < 16; c++) hs[c] += xk * sWs[k * 16 + c];
            ad += xk * swd[k];
        }
    }
    __half2 h2[8];
#pragma unroll
    for (int q = 0; q < 8; q++)
        h2[q] = __floats2half2_rn(hs[2 * q + 0], hs[2 * q + 1]);
    uint4 o0, o1;
    o0.x = *(unsigned int*)&h2[0]; o0.y = *(unsigned int*)&h2[1];
    o0.z = *(unsigned int*)&h2[2]; o0.w = *(unsigned int*)&h2[3];
    o1.x = *(unsigned int*)&h2[4]; o1.y = *(unsigned int*)&h2[5];
    o1.z = *(unsigned int*)&h2[6]; o1.w = *(unsigned int*)&h2[7];
    hso[(size_t)i * 2 + 0] = o0;
    hso[(size_t)i * 2 + 1] = o1;
    ado[i] = ad;
}

// ---------------- Kernel B: fill buckets, no atomics: pos = dst*STRIDE + rank ----------
__global__ void fill_kernel(
    const int* __restrict__ ub_src, const int* __restrict__ ub_dst,
    const unsigned short* __restrict__ rank_ub, int* __restrict__ bkt_ub,
    const int* __restrict__ bu_src, const int* __restrict__ bu_dst,
    const unsigned short* __restrict__ rank_bu, int* __restrict__ bkt_bu) {
    int t = blockIdx.x * blockDim.x + threadIdx.x;
    if (t >= NE / 8) return;
    int4 da0 = ((const int4*)ub_dst)[2 * t + 0];
    int4 da1 = ((const int4*)ub_dst)[2 * t + 1];
    int4 sa0 = ((const int4*)ub_src)[2 * t + 0];
    int4 sa1 = ((const int4*)ub_src)[2 * t + 1];
    uint4 ra = ((const uint4*)rank_ub)[t];
    int4 db0 = ((const int4*)bu_dst)[2 * t + 0];
    int4 db1 = ((const int4*)bu_dst)[2 * t + 1];
    int4 sb0 = ((const int4*)bu_src)[2 * t + 0];
    int4 sb1 = ((const int4*)bu_src)[2 * t + 1];
    uint4 rb = ((const uint4*)rank_bu)[t];

    int r0 = (int)(ra.x & 0xffffu), r1 = (int)(ra.x >> 16);
    int r2 = (int)(ra.y & 0xffffu), r3 = (int)(ra.y >> 16);
    int r4 = (int)(ra.z & 0xffffu), r5 = (int)(ra.z >> 16);
    int r6 = (int)(ra.w & 0xffffu), r7 = (int)(ra.w >> 16);
    int q0 = (int)(rb.x & 0xffffu), q1 = (int)(rb.x >> 16);
    int q2 = (int)(rb.y & 0xffffu), q3 = (int)(rb.y >> 16);
    int q4 = (int)(rb.z & 0xffffu), q5 = (int)(rb.z >> 16);
    int q6 = (int)(rb.w & 0xffffu), q7 = (int)(rb.w >> 16);

    if (r0 < STRIDE_B) bkt_ub[(size_t)da0.x * STRIDE_B + r0] = sa0.x;
    if (r1 < STRIDE_B) bkt_ub[(size_t)da0.y * STRIDE_B + r1] = sa0.y;
    if (r2 < STRIDE_B) bkt_ub[(size_t)da0.z * STRIDE_B + r2] = sa0.z;
    if (r3 < STRIDE_B) bkt_ub[(size_t)da0.w * STRIDE_B + r3] = sa0.w;
    if (r4 < STRIDE_B) bkt_ub[(size_t)da1.x * STRIDE_B + r4] = sa1.x;
    if (r5 < STRIDE_B) bkt_ub[(size_t)da1.y * STRIDE_B + r5] = sa1.y;
    if (r6 < STRIDE_B) bkt_ub[(size_t)da1.z * STRIDE_B + r6] = sa1.z;
    if (r7 < STRIDE_B) bkt_ub[(size_t)da1.w * STRIDE_B + r7] = sa1.w;
    if (q0 < STRIDE_U) bkt_bu[(size_t)db0.x * STRIDE_U + q0] = sb0.x;
    if (q1 < STRIDE_U) bkt_bu[(size_t)db0.y * STRIDE_U + q1] = sb0.y;
    if (q2 < STRIDE_U) bkt_bu[(size_t)db0.z * STRIDE_U + q2] = sb0.z;
    if (q3 < STRIDE_U) bkt_bu[(size_t)db0.w * STRIDE_U + q3] = sb0.w;
    if (q4 < STRIDE_U) bkt_bu[(size_t)db1.x * STRIDE_U + q4] = sb1.x;
    if (q5 < STRIDE_U) bkt_bu[(size_t)db1.y * STRIDE_U + q5] = sb1.y;
    if (q6 < STRIDE_U) bkt_bu[(size_t)db1.z * STRIDE_U + q6] = sb1.z;
    if (q7 < STRIDE_U) bkt_bu[(size_t)db1.w * STRIDE_U + q7] = sb1.w;
}

// ---------------- layer-1 aggregation (per-lane gather) + fused L2 transform ----------
template <int G, int STRIDE>
__device__ __forceinline__ void agg1_grp(
    int g, int lane,
    const int* __restrict__ cnt, const int* __restrict__ bkt,
    const float* __restrict__ ad_, const uint4* __restrict__ hs,
    const float* __restrict__ avec, const float* __restrict__ bias,
    const float* __restrict__ W2s, const float* __restrict__ W2d,
    const float* __restrict__ a2d,
    float* __restrict__ hs2_out, float* __restrict__ ad2_out) {
    float a[16];
#pragma unroll
    for (int c = 0; c < 16; c++) a[c] = __ldg(&avec[c]);
    float adv = __ldg(&ad_[g]);
    int deg = __ldg(&cnt[g]);
    if (deg > STRIDE) deg = STRIDE;
    const int* row = bkt + (size_t)g * STRIDE;

    float s = 0.f;
    float acc[16];
#pragma unroll
    for (int c = 0; c < 16; c++) acc[c] = 0.f;

    int i = lane;
    int src = (i < deg) ? __ldg(&row[i]) : 0;
    while (i < deg) {
        int inext = i + G;
        int src_next = (inext < deg) ? __ldg(&row[inext]) : 0;
        uint4 v0 = __ldg(&hs[(size_t)src * 2 + 0]);
        uint4 v1 = __ldg(&hs[(size_t)src * 2 + 1]);
        unsigned int w32[8] = {v0.x, v0.y, v0.z, v0.w, v1.x, v1.y, v1.z, v1.w};
        float h[16];
#pragma unroll
        for (int q = 0; q < 8; q++) {
            float2 f = __half22float2(*(__half2*)&w32[q]);
            h[2 * q + 0] = f.x;
            h[2 * q + 1] = f.y;
        }
        float es = 0.f;
#pragma unroll
        for (int c = 0; c < 16; c++) es += h[c] * a[c];
        float e = es + adv;
        e = (e > 0.f) ? e : 0.2f * e;
        float w = __expf(e);
        s += w;
#pragma unroll
        for (int c = 0; c < 16; c++) acc[c] += w * h[c];
        src = src_next;
        i = inext;
    }

#pragma unroll
    for (int off = G / 2; off; off >>= 1) {
        s += __shfl_xor_sync(0xffffffffu, s, off);
#pragma unroll
        for (int c = 0; c < 16; c++)
            acc[c] += __shfl_xor_sync(0xffffffffu, acc[c], off);
    }

    if (lane == 0) {
        float inv = 1.0f / (s + 1e-16f);
        float s0 = 0.f, s1 = 0.f, d0 = 0.f, d1 = 0.f;
#pragma unroll
        for (int c = 0; c < 16; c++) {
            float h = fmaxf(acc[c] * inv + __ldg(&bias[c]), 0.f);
            s0 += h * __ldg(&W2s[c * 2 + 0]);
            s1 += h * __ldg(&W2s[c * 2 + 1]);
            d0 += h * __ldg(&W2d[c * 2 + 0]);
            d1 += h * __ldg(&W2d[c * 2 + 1]);
        }
        *(float2*)(hs2_out + (size_t)g * 2) = make_float2(s0, s1);
        ad2_out[g] = d0 * __ldg(&a2d[0]) + d1 * __ldg(&a2d[1]);
    }
}

__global__ void agg1_all(
    const int* __restrict__ cnt_ub, const int* __restrict__ bkt_ub,
    const float* __restrict__ ad1b, const uint4* __restrict__ hs1u,
    const float* __restrict__ a1ubs, const float* __restrict__ b1ub,
    const float* __restrict__ W2bus, const float* __restrict__ W2ubd,
    const float* __restrict__ a2ubd,
    float* __restrict__ hs2b, float* __restrict__ ad2b,
    const int* __restrict__ cnt_bu, const int* __restrict__ bkt_bu,
    const float* __restrict__ ad1u, const uint4* __restrict__ hs1b,
    const float* __restrict__ a1bus, const float* __restrict__ b1bu,
    const float* __restrict__ W2ubs, const float* __restrict__ W2bud,
    const float* __restrict__ a2bud,
    float* __restrict__ hs2u, float* __restrict__ ad2u) {
    int w = blockIdx.x * (blockDim.x >> 5) + (threadIdx.x >> 5);
    int wl = threadIdx.x & 31;
    if (w < NB) {
        agg1_grp<32, STRIDE_B>(w, wl, cnt_ub, bkt_ub, ad1b, hs1u, a1ubs, b1ub,
                               W2bus, W2ubd, a2ubd, hs2b, ad2b);
    } else {
        int g = (w - NB) * 4 + (wl >> 3);     // 4 user dsts per warp, G=8
        if (g < NU)
            agg1_grp<8, STRIDE_U>(g, wl & 7, cnt_bu, bkt_bu, ad1u, hs1b, a1bus, b1bu,
                                  W2ubs, W2bud, a2bud, hs2u, ad2u);
    }
}

// ---------------- layer-2 aggregation (merged relations) ----------------
template <int G, int STRIDE>
__device__ __forceinline__ void agg2_grp(int g, int lane,
                                         const int* __restrict__ cnt, const int* __restrict__ bkt,
                                         const float* __restrict__ ad_, const float* __restrict__ hs,
                                         const float* __restrict__ avec, const float* __restrict__ bias,
                                         float* __restrict__ out) {
    float a0 = __ldg(&avec[0]), a1 = __ldg(&avec[1]);
    float adv = __ldg(&ad_[g]);
    int deg = __ldg(&cnt[g]);
    if (deg > STRIDE) deg = STRIDE;
    const int* row = bkt + (size_t)g * STRIDE;

    float s = 0.f, acc0 = 0.f, acc1 = 0.f;
    int i = lane;
    int src = (i < deg) ? __ldg(&row[i]) : 0;
    while (i < deg) {
        int inext = i + G;
        int src_next = (inext < deg) ? __ldg(&row[inext]) : 0;
        float2 v = *(const float2*)(hs + (size_t)src * 2);
        float e = v.x * a0 + v.y * a1 + adv;
        e = (e > 0.f) ? e : 0.2f * e;
        float w = __expf(e);
        s += w;
        acc0 += w * v.x;
        acc1 += w * v.y;
        src = src_next;
        i = inext;
    }
#pragma unroll
    for (int off = G / 2; off; off >>= 1) {
        s    += __shfl_xor_sync(0xffffffffu, s, off);
        acc0 += __shfl_xor_sync(0xffffffffu, acc0, off);
        acc1 += __shfl_xor_sync(0xffffffffu, acc1, off);
    }
    if (lane == 0) {
        float inv = 1.0f / (s + 1e-16f);
        *(float2*)(out + (size_t)g * 2) =
            make_float2(acc0 * inv + __ldg(&bias[0]), acc1 * inv + __ldg(&bias[1]));
    }
}

__global__ void agg2_all(
    const int* __restrict__ cnt_ub, const int* __restrict__ bkt_ub,
    const float* __restrict__ ad2b, const float* __restrict__ hs2u,
    const float* __restrict__ a2ubs, const float* __restrict__ b2ub,
    float* __restrict__ out_b,
    const int* __restrict__ cnt_bu, const int* __restrict__ bkt_bu,
    const float* __restrict__ ad2u, const float* __restrict__ hs2b,
    const float* __restrict__ a2bus, const float* __restrict__ b2bu,
    float* __restrict__ out_u) {
    int w = blockIdx.x * (blockDim.x >> 5) + (threadIdx.x >> 5);
    int wl = threadIdx.x & 31;
    if (w < NB) {
        agg2_grp<32, STRIDE_B>(w, wl, cnt_ub, bkt_ub, ad2b, hs2u, a2ubs, b2ub, out_b);
    } else {
        int g = (w - NB) * 4 + (wl >> 3);
        if (g < NU)
            agg2_grp<8, STRIDE_U>(g, wl & 7, cnt_bu, bkt_bu, ad2u, hs2b, a2bus, b2bu, out_u);
    }
}

// ---------------- host ----------------
static void* sym_addr(const void* symbol) {
    void* p = nullptr;
    cudaGetSymbolAddress(&p, symbol);
    return p;
}

extern "C" void kernel_launch(void* const* d_in, const int* in_sizes, int n_in,
                              void* d_out, int out_size) {
    const float* x_user  = (const float*)d_in[0];
    const float* x_badge = (const float*)d_in[1];
    const int* ub_src = (const int*)d_in[2];
    const int* ub_dst = (const int*)d_in[3];
    const int* bu_src = (const int*)d_in[4];
    const int* bu_dst = (const int*)d_in[5];

    int iW1ubs = 8, iW1ubd = 9, ia1ubs = 10, ia1ubd = 11, ib1ub = 12;
    int iW1bus, iW1bud, ia1bus, ia1bud, ib1bu;
    int iW2ubs, iW2ubd, ia2ubs, ia2ubd, ib2ub;
    int iW2bus, iW2bud, ia2bus, ia2bud, ib2bu;
    if (in_sizes[13] == 1024) {
        iW1bus = 13; iW1bud = 14; ia1bus = 15; ia1bud = 16; ib1bu = 17;
        iW2ubs = 18; iW2ubd = 19; ia2ubs = 20; ia2ubd = 21; ib2ub = 22;
        iW2bus = 23; iW2bud = 24; ia2bus = 25; ia2bud = 26; ib2bu = 27;
    } else {
        iW2ubs = 13; iW2ubd = 14; ia2ubs = 15; ia2ubd = 16; ib2ub = 17;
        iW1bus = 18; iW1bud = 19; ia1bus = 20; ia1bud = 21; ib1bu = 22;
        iW2bus = 23; iW2bud = 24; ia2bus = 25; ia2bud = 26; ib2bu = 27;
    }
#define FP(i) ((const float*)d_in[i])

    int* cnt     = (int*)sym_addr(g_cnt);
    int* cnt_bu  = cnt;
    int* cnt_ub  = cnt + NU;
    int* bkt_ub  = (int*)sym_addr(g_bkt_ub);
    int* bkt_bu  = (int*)sym_addr(g_bkt_bu);
    unsigned short* rank_ub = (unsigned short*)sym_addr(g_rank_ub);
    unsigned short* rank_bu = (unsigned short*)sym_addr(g_rank_bu);
    uint4* hs1u = (uint4*)sym_addr(g_hs1_u);
    uint4* hs1b = (uint4*)sym_addr(g_hs1_b);
    float* ad1u = (float*)sym_addr(g_ad1_u);
    float* ad1b = (float*)sym_addr(g_ad1_b);
    float* hs2u = (float*)sym_addr(g_hs2_u);
    float* hs2b = (float*)sym_addr(g_hs2_b);
    float* ad2u = (float*)sym_addr(g_ad2_u);
    float* ad2b = (float*)sym_addr(g_ad2_b);

    // ---- Kernel A: count + rank record + node transforms ----
    cudaMemsetAsync(cnt, 0, (NU + NB) * sizeof(int));
    count_node_kernel<<<GE8_BLOCKS + UBLK + BBLK, 256>>>(
        ub_dst, cnt_ub, rank_ub,
        bu_dst, cnt_bu, rank_bu,
        x_user, x_badge,
        FP(iW1ubs), FP(iW1bud), FP(ia1bud),
        FP(iW1bus), FP(iW1ubd), FP(ia1ubd),
        hs1u, ad1u, hs1b, ad1b);

    // ---- Kernel B: dependency-free bucket fill ----
    fill_kernel<<<GE8_BLOCKS, 256>>>(
        ub_src, ub_dst, rank_ub, bkt_ub,
        bu_src, bu_dst, rank_bu, bkt_bu);

    // ---- layer 1 aggregation + fused layer-2 node transform (one launch) ----
    {
        long warps = (long)NB + (NU + 3) / 4;
        int blocks = (int)((warps * 32 + 255) / 256);
        agg1_all<<<blocks, 256>>>(
            cnt_ub, bkt_ub, ad1b, hs1u, FP(ia1ubs), FP(ib1ub),
            FP(iW2bus), FP(iW2ubd), FP(ia2ubd), hs2b, ad2b,
            cnt_bu, bkt_bu, ad1u, hs1b, FP(ia1bus), FP(ib1bu),
            FP(iW2ubs), FP(iW2bud), FP(ia2bud), hs2u, ad2u);
    }

    // ---- layer 2 aggregation -> outputs (one launch) ----
    float* out = (float*)d_out;   // [ou (200000x2) | ob (50000x2)]
    {
        long warps = (long)NB + (NU + 3) / 4;
        int blocks = (int)((warps * 32 + 255) / 256);
        agg2_all<<<blocks, 256>>>(
            cnt_ub, bkt_ub, ad2b, hs2u, FP(ia2ubs), FP(ib2ub), out + (size_t)NU * 2,
            cnt_bu, bkt_bu, ad2u, hs2b, FP(ia2bus), FP(ib2bu), out);
    }
}

// round 13
// speedup vs baseline: 1.1223x; 1.1223x over previous
#include <cuda_runtime.h>
#include <cuda_fp16.h>
#include <math.h>

#define NU 200000
#define NB 50000
#define NE 5000000
#define STRIDE_B 192
#define STRIDE_U 64

// ---------------- scratch ----------------
__device__ int g_cnt[NU + NB];
__device__ int g_bkt_ub[(size_t)NB * STRIDE_B];
__device__ int g_bkt_bu[(size_t)NU * STRIDE_U];

__device__ uint4 g_hs1_u[NU * 2];         // fp16 rows: 16 halves = 32B
__device__ uint4 g_hs1_b[NB * 2];
__device__ float g_ad1_u[NU];
__device__ float g_ad1_b[NB];
__device__ float g_hs2_u[NU * 2], g_hs2_b[NB * 2];
__device__ float g_ad2_u[NU];
__device__ float g_ad2_b[NB];

#define GE4_BLOCKS ((NE / 4 + 255) / 256)
#define UBLK ((NU + 255) / 256)
#define BBLK ((NB + 255) / 256)

// ---------------- fused build (4 edges/rel/thread, ~35 regs) + node transform ----------
// R2 evidence: this build shape ran at occ 86% / 132 us. Node branch computes
// 8 channels per thread (2x blocks) to keep its register count comparable, so
// the fused kernel keeps high occupancy naturally (no cap, no spills).
__global__ void build_node_kernel(
    const int* __restrict__ ub_src, const int* __restrict__ ub_dst,
    int* __restrict__ cnt_ub, int* __restrict__ bkt_ub,
    const int* __restrict__ bu_src, const int* __restrict__ bu_dst,
    int* __restrict__ cnt_bu, int* __restrict__ bkt_bu,
    const float* __restrict__ xu, const float* __restrict__ xb,
    const float* __restrict__ Ws_u, const float* __restrict__ Wd_u,
    const float* __restrict__ avd_u,
    const float* __restrict__ Ws_b, const float* __restrict__ Wd_b,
    const float* __restrict__ avd_b,
    uint4* __restrict__ hs_u, float* __restrict__ ad_u,
    uint4* __restrict__ hs_b, float* __restrict__ ad_b) {
    __shared__ float sW[64 * 8], swd[64];

    if (blockIdx.x < GE4_BLOCKS) {
        // ---------- bucket build: 4 edges per relation per thread ----------
        int t = blockIdx.x * 256 + threadIdx.x;
        if (t >= NE / 4) return;
        int4 da = ((const int4*)ub_dst)[t];
        int4 sa = ((const int4*)ub_src)[t];
        int4 db = ((const int4*)bu_dst)[t];
        int4 sb = ((const int4*)bu_src)[t];

        int r0 = atomicAdd(&cnt_ub[da.x], 1);
        int r1 = atomicAdd(&cnt_ub[da.y], 1);
        int r2 = atomicAdd(&cnt_ub[da.z], 1);
        int r3 = atomicAdd(&cnt_ub[da.w], 1);
        int q0 = atomicAdd(&cnt_bu[db.x], 1);
        int q1 = atomicAdd(&cnt_bu[db.y], 1);
        int q2 = atomicAdd(&cnt_bu[db.z], 1);
        int q3 = atomicAdd(&cnt_bu[db.w], 1);

        if (r0 < STRIDE_B) bkt_ub[(size_t)da.x * STRIDE_B + r0] = sa.x;
        if (r1 < STRIDE_B) bkt_ub[(size_t)da.y * STRIDE_B + r1] = sa.y;
        if (r2 < STRIDE_B) bkt_ub[(size_t)da.z * STRIDE_B + r2] = sa.z;
        if (r3 < STRIDE_B) bkt_ub[(size_t)da.w * STRIDE_B + r3] = sa.w;
        if (q0 < STRIDE_U) bkt_bu[(size_t)db.x * STRIDE_U + q0] = sb.x;
        if (q1 < STRIDE_U) bkt_bu[(size_t)db.y * STRIDE_U + q1] = sb.y;
        if (q2 < STRIDE_U) bkt_bu[(size_t)db.z * STRIDE_U + q2] = sb.z;
        if (q3 < STRIDE_U) bkt_bu[(size_t)db.w * STRIDE_U + q3] = sb.w;
        return;
    }

    // ---------- node transform: 8 channels per thread (2 blocks per node chunk) ----------
    int nb = blockIdx.x - GE4_BLOCKS;
    bool isU = (nb < 2 * UBLK);
    int nb2 = isU ? nb : nb - 2 * UBLK;
    int half = nb2 & 1;                    // 0: channels 0-7 (+ad), 1: channels 8-15
    int chunk = nb2 >> 1;
    const float* x   = isU ? xu : xb;
    const float* Ws  = isU ? Ws_u : Ws_b;
    const float* Wd  = isU ? Wd_u : Wd_b;
    const float* avd = isU ? avd_u : avd_b;
    uint4* hso       = isU ? hs_u : hs_b;
    float* ado       = isU ? ad_u : ad_b;
    int n            = isU ? NU : NB;
    int i = chunk * 256 + threadIdx.x;

    // load the 64x8 half of Ws this block needs
    for (int j = threadIdx.x; j < 512; j += 256) {
        int k = j >> 3, c = j & 7;
        sW[j] = Ws[k * 16 + half * 8 + c];
    }
    if (half == 0 && threadIdx.x < 64) {
        float acc = 0.f;
#pragma unroll
        for (int c = 0; c < 16; c++) acc += Wd[threadIdx.x * 16 + c] * avd[c];
        swd[threadIdx.x] = acc;
    }
    __syncthreads();
    if (i >= n) return;

    float hs[8];
#pragma unroll
    for (int c = 0; c < 8; c++) hs[c] = 0.f;
    float ad = 0.f;
    const float4* xp = (const float4*)(x + (size_t)i * 64);
#pragma unroll 4
    for (int q = 0; q < 16; q++) {
        float4 v = xp[q];
#pragma unroll
        for (int kk = 0; kk < 4; kk++) {
            float xk = (kk == 0) ? v.x : (kk == 1) ? v.y : (kk == 2) ? v.z : v.w;
            int k = q * 4 + kk;
#pragma unroll
            for (int c = 0; c < 8; c++) hs[c] += xk * sW[k * 8 + c];
            if (half == 0) ad += xk * swd[k];
        }
    }
    __half2 h2[4];
#pragma unroll
    for (int q = 0; q < 4; q++)
        h2[q] = __floats2half2_rn(hs[2 * q + 0], hs[2 * q + 1]);
    uint4 o;
    o.x = *(unsigned int*)&h2[0]; o.y = *(unsigned int*)&h2[1];
    o.z = *(unsigned int*)&h2[2]; o.w = *(unsigned int*)&h2[3];
    hso[(size_t)i * 2 + half] = o;
    if (half == 0) ado[i] = ad;
}

// ---------------- layer-1 aggregation (per-lane gather) + fused L2 transform ----------
template <int G, int STRIDE>
__device__ __forceinline__ void agg1_grp(
    int g, int lane,
    const int* __restrict__ cnt, const int* __restrict__ bkt,
    const float* __restrict__ ad_, const uint4* __restrict__ hs,
    const float* __restrict__ avec, const float* __restrict__ bias,
    const float* __restrict__ W2s, const float* __restrict__ W2d,
    const float* __restrict__ a2d,
    float* __restrict__ hs2_out, float* __restrict__ ad2_out) {
    float a[16];
#pragma unroll
    for (int c = 0; c < 16; c++) a[c] = __ldg(&avec[c]);
    float adv = __ldg(&ad_[g]);
    int deg = __ldg(&cnt[g]);
    if (deg > STRIDE) deg = STRIDE;
    const int* row = bkt + (size_t)g * STRIDE;

    float s = 0.f;
    float acc[16];
#pragma unroll
    for (int c = 0; c < 16; c++) acc[c] = 0.f;

    int i = lane;
    int src = (i < deg) ? __ldg(&row[i]) : 0;
    while (i < deg) {
        int inext = i + G;
        int src_next = (inext < deg) ? __ldg(&row[inext]) : 0;
        uint4 v0 = __ldg(&hs[(size_t)src * 2 + 0]);
        uint4 v1 = __ldg(&hs[(size_t)src * 2 + 1]);
        unsigned int w32[8] = {v0.x, v0.y, v0.z, v0.w, v1.x, v1.y, v1.z, v1.w};
        float h[16];
#pragma unroll
        for (int q = 0; q < 8; q++) {
            float2 f = __half22float2(*(__half2*)&w32[q]);
            h[2 * q + 0] = f.x;
            h[2 * q + 1] = f.y;
        }
        float es = 0.f;
#pragma unroll
        for (int c = 0; c < 16; c++) es += h[c] * a[c];
        float e = es + adv;
        e = (e > 0.f) ? e : 0.2f * e;
        float w = __expf(e);
        s += w;
#pragma unroll
        for (int c = 0; c < 16; c++) acc[c] += w * h[c];
        src = src_next;
        i = inext;
    }

#pragma unroll
    for (int off = G / 2; off; off >>= 1) {
        s += __shfl_xor_sync(0xffffffffu, s, off);
#pragma unroll
        for (int c = 0; c < 16; c++)
            acc[c] += __shfl_xor_sync(0xffffffffu, acc[c], off);
    }

    if (lane == 0) {
        float inv = 1.0f / (s + 1e-16f);
        float s0 = 0.f, s1 = 0.f, d0 = 0.f, d1 = 0.f;
#pragma unroll
        for (int c = 0; c < 16; c++) {
            float h = fmaxf(acc[c] * inv + __ldg(&bias[c]), 0.f);
            s0 += h * __ldg(&W2s[c * 2 + 0]);
            s1 += h * __ldg(&W2s[c * 2 + 1]);
            d0 += h * __ldg(&W2d[c * 2 + 0]);
            d1 += h * __ldg(&W2d[c * 2 + 1]);
        }
        *(float2*)(hs2_out + (size_t)g * 2) = make_float2(s0, s1);
        ad2_out[g] = d0 * __ldg(&a2d[0]) + d1 * __ldg(&a2d[1]);
    }
}

__global__ void agg1_all(
    const int* __restrict__ cnt_ub, const int* __restrict__ bkt_ub,
    const float* __restrict__ ad1b, const uint4* __restrict__ hs1u,
    const float* __restrict__ a1ubs, const float* __restrict__ b1ub,
    const float* __restrict__ W2bus, const float* __restrict__ W2ubd,
    const float* __restrict__ a2ubd,
    float* __restrict__ hs2b, float* __restrict__ ad2b,
    const int* __restrict__ cnt_bu, const int* __restrict__ bkt_bu,
    const float* __restrict__ ad1u, const uint4* __restrict__ hs1b,
    const float* __restrict__ a1bus, const float* __restrict__ b1bu,
    const float* __restrict__ W2ubs, const float* __restrict__ W2bud,
    const float* __restrict__ a2bud,
    float* __restrict__ hs2u, float* __restrict__ ad2u) {
    int w = blockIdx.x * (blockDim.x >> 5) + (threadIdx.x >> 5);
    int wl = threadIdx.x & 31;
    if (w < NB) {
        agg1_grp<32, STRIDE_B>(w, wl, cnt_ub, bkt_ub, ad1b, hs1u, a1ubs, b1ub,
                               W2bus, W2ubd, a2ubd, hs2b, ad2b);
    } else {
        int g = (w - NB) * 4 + (wl >> 3);     // 4 user dsts per warp, G=8
        if (g < NU)
            agg1_grp<8, STRIDE_U>(g, wl & 7, cnt_bu, bkt_bu, ad1u, hs1b, a1bus, b1bu,
                                  W2ubs, W2bud, a2bud, hs2u, ad2u);
    }
}

// ---------------- layer-2 aggregation (merged relations) ----------------
template <int G, int STRIDE>
__device__ __forceinline__ void agg2_grp(int g, int lane,
                                         const int* __restrict__ cnt, const int* __restrict__ bkt,
                                         const float* __restrict__ ad_, const float* __restrict__ hs,
                                         const float* __restrict__ avec, const float* __restrict__ bias,
                                         float* __restrict__ out) {
    float a0 = __ldg(&avec[0]), a1 = __ldg(&avec[1]);
    float adv = __ldg(&ad_[g]);
    int deg = __ldg(&cnt[g]);
    if (deg > STRIDE) deg = STRIDE;
    const int* row = bkt + (size_t)g * STRIDE;

    float s = 0.f, acc0 = 0.f, acc1 = 0.f;
    int i = lane;
    int src = (i < deg) ? __ldg(&row[i]) : 0;
    while (i < deg) {
        int inext = i + G;
        int src_next = (inext < deg) ? __ldg(&row[inext]) : 0;
        float2 v = *(const float2*)(hs + (size_t)src * 2);
        float e = v.x * a0 + v.y * a1 + adv;
        e = (e > 0.f) ? e : 0.2f * e;
        float w = __expf(e);
        s += w;
        acc0 += w * v.x;
        acc1 += w * v.y;
        src = src_next;
        i = inext;
    }
#pragma unroll
    for (int off = G / 2; off; off >>= 1) {
        s    += __shfl_xor_sync(0xffffffffu, s, off);
        acc0 += __shfl_xor_sync(0xffffffffu, acc0, off);
        acc1 += __shfl_xor_sync(0xffffffffu, acc1, off);
    }
    if (lane == 0) {
        float inv = 1.0f / (s + 1e-16f);
        *(float2*)(out + (size_t)g * 2) =
            make_float2(acc0 * inv + __ldg(&bias[0]), acc1 * inv + __ldg(&bias[1]));
    }
}

__global__ void agg2_all(
    const int* __restrict__ cnt_ub, const int* __restrict__ bkt_ub,
    const float* __restrict__ ad2b, const float* __restrict__ hs2u,
    const float* __restrict__ a2ubs, const float* __restrict__ b2ub,
    float* __restrict__ out_b,
    const int* __restrict__ cnt_bu, const int* __restrict__ bkt_bu,
    const float* __restrict__ ad2u, const float* __restrict__ hs2b,
    const float* __restrict__ a2bus, const float* __restrict__ b2bu,
    float* __restrict__ out_u) {
    int w = blockIdx.x * (blockDim.x >> 5) + (threadIdx.x >> 5);
    int wl = threadIdx.x & 31;
    if (w < NB) {
        agg2_grp<32, STRIDE_B>(w, wl, cnt_ub, bkt_ub, ad2b, hs2u, a2ubs, b2ub, out_b);
    } else {
        int g = (w - NB) * 4 + (wl >> 3);
        if (g < NU)
            agg2_grp<8, STRIDE_U>(g, wl & 7, cnt_bu, bkt_bu, ad2u, hs2b, a2bus, b2bu, out_u);
    }
}

// ---------------- host ----------------
static void* sym_addr(const void* symbol) {
    void* p = nullptr;
    cudaGetSymbolAddress(&p, symbol);
    return p;
}

extern "C" void kernel_launch(void* const* d_in, const int* in_sizes, int n_in,
                              void* d_out, int out_size) {
    const float* x_user  = (const float*)d_in[0];
    const float* x_badge = (const float*)d_in[1];
    const int* ub_src = (const int*)d_in[2];
    const int* ub_dst = (const int*)d_in[3];
    const int* bu_src = (const int*)d_in[4];
    const int* bu_dst = (const int*)d_in[5];

    int iW1ubs = 8, iW1ubd = 9, ia1ubs = 10, ia1ubd = 11, ib1ub = 12;
    int iW1bus, iW1bud, ia1bus, ia1bud, ib1bu;
    int iW2ubs, iW2ubd, ia2ubs, ia2ubd, ib2ub;
    int iW2bus, iW2bud, ia2bus, ia2bud, ib2bu;
    if (in_sizes[13] == 1024) {
        iW1bus = 13; iW1bud = 14; ia1bus = 15; ia1bud = 16; ib1bu = 17;
        iW2ubs = 18; iW2ubd = 19; ia2ubs = 20; ia2ubd = 21; ib2ub = 22;
        iW2bus = 23; iW2bud = 24; ia2bus = 25; ia2bud = 26; ib2bu = 27;
    } else {
        iW2ubs = 13; iW2ubd = 14; ia2ubs = 15; ia2ubd = 16; ib2ub = 17;
        iW1bus = 18; iW1bud = 19; ia1bus = 20; ia1bud = 21; ib1bu = 22;
        iW2bus = 23; iW2bud = 24; ia2bus = 25; ia2bud = 26; ib2bu = 27;
    }
#define FP(i) ((const float*)d_in[i])

    int* cnt     = (int*)sym_addr(g_cnt);
    int* cnt_bu  = cnt;
    int* cnt_ub  = cnt + NU;
    int* bkt_ub  = (int*)sym_addr(g_bkt_ub);
    int* bkt_bu  = (int*)sym_addr(g_bkt_bu);
    uint4* hs1u = (uint4*)sym_addr(g_hs1_u);
    uint4* hs1b = (uint4*)sym_addr(g_hs1_b);
    float* ad1u = (float*)sym_addr(g_ad1_u);
    float* ad1b = (float*)sym_addr(g_ad1_b);
    float* hs2u = (float*)sym_addr(g_hs2_u);
    float* hs2b = (float*)sym_addr(g_hs2_b);
    float* ad2u = (float*)sym_addr(g_ad2_u);
    float* ad2b = (float*)sym_addr(g_ad2_b);

    // ---- bucket build + layer-1 node transforms (one fused launch) ----
    cudaMemsetAsync(cnt, 0, (NU + NB) * sizeof(int));
    build_node_kernel<<<GE4_BLOCKS + 2 * (UBLK + BBLK), 256>>>(
        ub_src, ub_dst, cnt_ub, bkt_ub,
        bu_src, bu_dst, cnt_bu, bkt_bu,
        x_user, x_badge,
        FP(iW1ubs), FP(iW1bud), FP(ia1bud),
        FP(iW1bus), FP(iW1ubd), FP(ia1ubd),
        hs1u, ad1u, hs1b, ad1b);

    // ---- layer 1 aggregation + fused layer-2 node transform (one launch) ----
    {
        long warps = (long)NB + (NU + 3) / 4;
        int blocks = (int)((warps * 32 + 255) / 256);
        agg1_all<<<blocks, 256>>>(
            cnt_ub, bkt_ub, ad1b, hs1u, FP(ia1ubs), FP(ib1ub),
            FP(iW2bus), FP(iW2ubd), FP(ia2ubd), hs2b, ad2b,
            cnt_bu, bkt_bu, ad1u, hs1b, FP(ia1bus), FP(ib1bu),
            FP(iW2ubs), FP(iW2bud), FP(ia2bud), hs2u, ad2u);
    }

    // ---- layer 2 aggregation -> outputs (one launch) ----
    float* out = (float*)d_out;   // [ou (200000x2) | ob (50000x2)]
    {
        long warps = (long)NB + (NU + 3) / 4;
        int blocks = (int)((warps * 32 + 255) / 256);
        agg2_all<<<blocks, 256>>>(
            cnt_ub, bkt_ub, ad2b, hs2u, FP(ia2ubs), FP(ib2ub), out + (size_t)NU * 2,
            cnt_bu, bkt_bu, ad2u, hs2b, FP(ia2bus), FP(ib2bu), out);
    }
}

// round 14
// speedup vs baseline: 1.2564x; 1.1195x over previous
#include <cuda_runtime.h>
#include <cuda_fp16.h>
#include <math.h>

#define NU 200000
#define NB 50000
#define NE 5000000
#define STRIDE_B 192
#define STRIDE_U 64

// ---------------- scratch ----------------
__device__ int g_cnt[NU + NB];
__device__ int g_bkt_ub[(size_t)NB * STRIDE_B];
__device__ int g_bkt_bu[(size_t)NU * STRIDE_U];

__device__ uint4 g_hs1_u[NU * 2];         // fp16 rows: 16 halves = 32B
__device__ uint4 g_hs1_b[NB * 2];
__device__ float g_ad1_u[NU];
__device__ float g_ad1_b[NB];
__device__ float g_hs2_u[NU * 2], g_hs2_b[NB * 2];
__device__ float g_ad2_u[NU];
__device__ float g_ad2_b[NB];

#define GE8_BLOCKS ((NE / 8 + 255) / 256)          // 2442
#define UBLK ((NU + 255) / 256)                     // 782
#define BBLK ((NB + 255) / 256)                     // 196
#define NODE_BLOCKS (UBLK + BBLK)                   // 978
// interleave: per 7-block group, 5 build + 2 node (2442:978 ~ 2.5:1)
#define NGROUPS ((GE8_BLOCKS + 4) / 5)              // 489
#define TOTAL_BLOCKS (NGROUPS * 7)                  // 3423

// ---------------- fused build (R11 exact bodies) + node transform, interleaved ----------
__global__ void build_node_kernel(
    const int* __restrict__ ub_src, const int* __restrict__ ub_dst,
    int* __restrict__ cnt_ub, int* __restrict__ bkt_ub,
    const int* __restrict__ bu_src, const int* __restrict__ bu_dst,
    int* __restrict__ cnt_bu, int* __restrict__ bkt_bu,
    const float* __restrict__ xu, const float* __restrict__ xb,
    const float* __restrict__ Ws_u, const float* __restrict__ Wd_u,
    const float* __restrict__ avd_u,
    const float* __restrict__ Ws_b, const float* __restrict__ Wd_b,
    const float* __restrict__ avd_b,
    uint4* __restrict__ hs_u, float* __restrict__ ad_u,
    uint4* __restrict__ hs_b, float* __restrict__ ad_b) {
    __shared__ float sWs[64 * 16], swd[64];

    int grp = blockIdx.x / 7;
    int sub = blockIdx.x % 7;
    bool isBuild = (sub < 5);
    int bid = isBuild ? (grp * 5 + sub) : (grp * 2 + (sub - 5));

    if (isBuild) {
        if (bid >= GE8_BLOCKS) return;
        // ---------- bucket build: 8 edges/rel/thread, both relations interleaved ----------
        int t = bid * 256 + threadIdx.x;
        if (t >= NE / 8) return;
        int4 da0 = ((const int4*)ub_dst)[2 * t + 0];
        int4 da1 = ((const int4*)ub_dst)[2 * t + 1];
        int4 db0 = ((const int4*)bu_dst)[2 * t + 0];
        int4 db1 = ((const int4*)bu_dst)[2 * t + 1];
        int4 sa0 = ((const int4*)ub_src)[2 * t + 0];
        int4 sa1 = ((const int4*)ub_src)[2 * t + 1];
        int4 sb0 = ((const int4*)bu_src)[2 * t + 0];
        int4 sb1 = ((const int4*)bu_src)[2 * t + 1];

        int r0 = atomicAdd(&cnt_ub[da0.x], 1);
        int r1 = atomicAdd(&cnt_ub[da0.y], 1);
        int r2 = atomicAdd(&cnt_ub[da0.z], 1);
        int r3 = atomicAdd(&cnt_ub[da0.w], 1);
        int r4 = atomicAdd(&cnt_ub[da1.x], 1);
        int r5 = atomicAdd(&cnt_ub[da1.y], 1);
        int r6 = atomicAdd(&cnt_ub[da1.z], 1);
        int r7 = atomicAdd(&cnt_ub[da1.w], 1);
        int q0 = atomicAdd(&cnt_bu[db0.x], 1);
        int q1 = atomicAdd(&cnt_bu[db0.y], 1);
        int q2 = atomicAdd(&cnt_bu[db0.z], 1);
        int q3 = atomicAdd(&cnt_bu[db0.w], 1);
        int q4 = atomicAdd(&cnt_bu[db1.x], 1);
        int q5 = atomicAdd(&cnt_bu[db1.y], 1);
        int q6 = atomicAdd(&cnt_bu[db1.z], 1);
        int q7 = atomicAdd(&cnt_bu[db1.w], 1);

        if (r0 < STRIDE_B) bkt_ub[(size_t)da0.x * STRIDE_B + r0] = sa0.x;
        if (r1 < STRIDE_B) bkt_ub[(size_t)da0.y * STRIDE_B + r1] = sa0.y;
        if (r2 < STRIDE_B) bkt_ub[(size_t)da0.z * STRIDE_B + r2] = sa0.z;
        if (r3 < STRIDE_B) bkt_ub[(size_t)da0.w * STRIDE_B + r3] = sa0.w;
        if (r4 < STRIDE_B) bkt_ub[(size_t)da1.x * STRIDE_B + r4] = sa1.x;
        if (r5 < STRIDE_B) bkt_ub[(size_t)da1.y * STRIDE_B + r5] = sa1.y;
        if (r6 < STRIDE_B) bkt_ub[(size_t)da1.z * STRIDE_B + r6] = sa1.z;
        if (r7 < STRIDE_B) bkt_ub[(size_t)da1.w * STRIDE_B + r7] = sa1.w;
        if (q0 < STRIDE_U) bkt_bu[(size_t)db0.x * STRIDE_U + q0] = sb0.x;
        if (q1 < STRIDE_U) bkt_bu[(size_t)db0.y * STRIDE_U + q1] = sb0.y;
        if (q2 < STRIDE_U) bkt_bu[(size_t)db0.z * STRIDE_U + q2] = sb0.z;
        if (q3 < STRIDE_U) bkt_bu[(size_t)db0.w * STRIDE_U + q3] = sb0.w;
        if (q4 < STRIDE_U) bkt_bu[(size_t)db1.x * STRIDE_U + q4] = sb1.x;
        if (q5 < STRIDE_U) bkt_bu[(size_t)db1.y * STRIDE_U + q5] = sb1.y;
        if (q6 < STRIDE_U) bkt_bu[(size_t)db1.z * STRIDE_U + q6] = sb1.z;
        if (q7 < STRIDE_U) bkt_bu[(size_t)db1.w * STRIDE_U + q7] = sb1.w;
        return;
    }

    // ---------- node transform (R11 exact: hd eliminated via wdvec = Wd @ avd) ----------
    if (bid >= NODE_BLOCKS) return;
    bool isU = (bid < UBLK);
    const float* x   = isU ? xu : xb;
    const float* Ws  = isU ? Ws_u : Ws_b;
    const float* Wd  = isU ? Wd_u : Wd_b;
    const float* avd = isU ? avd_u : avd_b;
    uint4* hso       = isU ? hs_u : hs_b;
    float* ado       = isU ? ad_u : ad_b;
    int n            = isU ? NU : NB;
    int i = (isU ? bid : bid - UBLK) * 256 + threadIdx.x;

    for (int j = threadIdx.x; j < 1024; j += 256) sWs[j] = Ws[j];
    if (threadIdx.x < 64) {
        float acc = 0.f;
#pragma unroll
        for (int c = 0; c < 16; c++) acc += Wd[threadIdx.x * 16 + c] * avd[c];
        swd[threadIdx.x] = acc;
    }
    __syncthreads();
    if (i >= n) return;

    float hs[16];
#pragma unroll
    for (int c = 0; c < 16; c++) hs[c] = 0.f;
    float ad = 0.f;
    const float4* xp = (const float4*)(x + (size_t)i * 64);
#pragma unroll 4
    for (int q = 0; q < 16; q++) {
        float4 v = xp[q];
#pragma unroll
        for (int kk = 0; kk < 4; kk++) {
            float xk = (kk == 0) ? v.x : (kk == 1) ? v.y : (kk == 2) ? v.z : v.w;
            int k = q * 4 + kk;
#pragma unroll
            for (int c = 0; c < 16; c++) hs[c] += xk * sWs[k * 16 + c];
            ad += xk * swd[k];
        }
    }
    __half2 h2[8];
#pragma unroll
    for (int q = 0; q < 8; q++)
        h2[q] = __floats2half2_rn(hs[2 * q + 0], hs[2 * q + 1]);
    uint4 o0, o1;
    o0.x = *(unsigned int*)&h2[0]; o0.y = *(unsigned int*)&h2[1];
    o0.z = *(unsigned int*)&h2[2]; o0.w = *(unsigned int*)&h2[3];
    o1.x = *(unsigned int*)&h2[4]; o1.y = *(unsigned int*)&h2[5];
    o1.z = *(unsigned int*)&h2[6]; o1.w = *(unsigned int*)&h2[7];
    hso[(size_t)i * 2 + 0] = o0;
    hso[(size_t)i * 2 + 1] = o1;
    ado[i] = ad;
}

// ---------------- layer-1 aggregation (per-lane gather) + fused L2 transform ----------
template <int G, int STRIDE>
__device__ __forceinline__ void agg1_grp(
    int g, int lane,
    const int* __restrict__ cnt, const int* __restrict__ bkt,
    const float* __restrict__ ad_, const uint4* __restrict__ hs,
    const float* __restrict__ avec, const float* __restrict__ bias,
    const float* __restrict__ W2s, const float* __restrict__ W2d,
    const float* __restrict__ a2d,
    float* __restrict__ hs2_out, float* __restrict__ ad2_out) {
    float a[16];
#pragma unroll
    for (int c = 0; c < 16; c++) a[c] = __ldg(&avec[c]);
    float adv = __ldg(&ad_[g]);
    int deg = __ldg(&cnt[g]);
    if (deg > STRIDE) deg = STRIDE;
    const int* row = bkt + (size_t)g * STRIDE;

    float s = 0.f;
    float acc[16];
#pragma unroll
    for (int c = 0; c < 16; c++) acc[c] = 0.f;

    int i = lane;
    int src = (i < deg) ? __ldg(&row[i]) : 0;
    while (i < deg) {
        int inext = i + G;
        int src_next = (inext < deg) ? __ldg(&row[inext]) : 0;
        uint4 v0 = __ldg(&hs[(size_t)src * 2 + 0]);
        uint4 v1 = __ldg(&hs[(size_t)src * 2 + 1]);
        unsigned int w32[8] = {v0.x, v0.y, v0.z, v0.w, v1.x, v1.y, v1.z, v1.w};
        float h[16];
#pragma unroll
        for (int q = 0; q < 8; q++) {
            float2 f = __half22float2(*(__half2*)&w32[q]);
            h[2 * q + 0] = f.x;
            h[2 * q + 1] = f.y;
        }
        float es = 0.f;
#pragma unroll
        for (int c = 0; c < 16; c++) es += h[c] * a[c];
        float e = es + adv;
        e = (e > 0.f) ? e : 0.2f * e;
        float w = __expf(e);
        s += w;
#pragma unroll
        for (int c = 0; c < 16; c++) acc[c] += w * h[c];
        src = src_next;
        i = inext;
    }

#pragma unroll
    for (int off = G / 2; off; off >>= 1) {
        s += __shfl_xor_sync(0xffffffffu, s, off);
#pragma unroll
        for (int c = 0; c < 16; c++)
            acc[c] += __shfl_xor_sync(0xffffffffu, acc[c], off);
    }

    if (lane == 0) {
        float inv = 1.0f / (s + 1e-16f);
        float s0 = 0.f, s1 = 0.f, d0 = 0.f, d1 = 0.f;
#pragma unroll
        for (int c = 0; c < 16; c++) {
            float h = fmaxf(acc[c] * inv + __ldg(&bias[c]), 0.f);
            s0 += h * __ldg(&W2s[c * 2 + 0]);
            s1 += h * __ldg(&W2s[c * 2 + 1]);
            d0 += h * __ldg(&W2d[c * 2 + 0]);
            d1 += h * __ldg(&W2d[c * 2 + 1]);
        }
        *(float2*)(hs2_out + (size_t)g * 2) = make_float2(s0, s1);
        ad2_out[g] = d0 * __ldg(&a2d[0]) + d1 * __ldg(&a2d[1]);
    }
}

__global__ void agg1_all(
    const int* __restrict__ cnt_ub, const int* __restrict__ bkt_ub,
    const float* __restrict__ ad1b, const uint4* __restrict__ hs1u,
    const float* __restrict__ a1ubs, const float* __restrict__ b1ub,
    const float* __restrict__ W2bus, const float* __restrict__ W2ubd,
    const float* __restrict__ a2ubd,
    float* __restrict__ hs2b, float* __restrict__ ad2b,
    const int* __restrict__ cnt_bu, const int* __restrict__ bkt_bu,
    const float* __restrict__ ad1u, const uint4* __restrict__ hs1b,
    const float* __restrict__ a1bus, const float* __restrict__ b1bu,
    const float* __restrict__ W2ubs, const float* __restrict__ W2bud,
    const float* __restrict__ a2bud,
    float* __restrict__ hs2u, float* __restrict__ ad2u) {
    int w = blockIdx.x * (blockDim.x >> 5) + (threadIdx.x >> 5);
    int wl = threadIdx.x & 31;
    if (w < NB) {
        agg1_grp<32, STRIDE_B>(w, wl, cnt_ub, bkt_ub, ad1b, hs1u, a1ubs, b1ub,
                               W2bus, W2ubd, a2ubd, hs2b, ad2b);
    } else {
        int g = (w - NB) * 4 + (wl >> 3);     // 4 user dsts per warp, G=8
        if (g < NU)
            agg1_grp<8, STRIDE_U>(g, wl & 7, cnt_bu, bkt_bu, ad1u, hs1b, a1bus, b1bu,
                                  W2ubs, W2bud, a2bud, hs2u, ad2u);
    }
}

// ---------------- layer-2 aggregation (merged relations) ----------------
template <int G, int STRIDE>
__device__ __forceinline__ void agg2_grp(int g, int lane,
                                         const int* __restrict__ cnt, const int* __restrict__ bkt,
                                         const float* __restrict__ ad_, const float* __restrict__ hs,
                                         const float* __restrict__ avec, const float* __restrict__ bias,
                                         float* __restrict__ out) {
    float a0 = __ldg(&avec[0]), a1 = __ldg(&avec[1]);
    float adv = __ldg(&ad_[g]);
    int deg = __ldg(&cnt[g]);
    if (deg > STRIDE) deg = STRIDE;
    const int* row = bkt + (size_t)g * STRIDE;

    float s = 0.f, acc0 = 0.f, acc1 = 0.f;
    int i = lane;
    int src = (i < deg) ? __ldg(&row[i]) : 0;
    while (i < deg) {
        int inext = i + G;
        int src_next = (inext < deg) ? __ldg(&row[inext]) : 0;
        float2 v = *(const float2*)(hs + (size_t)src * 2);
        float e = v.x * a0 + v.y * a1 + adv;
        e = (e > 0.f) ? e : 0.2f * e;
        float w = __expf(e);
        s += w;
        acc0 += w * v.x;
        acc1 += w * v.y;
        src = src_next;
        i = inext;
    }
#pragma unroll
    for (int off = G / 2; off; off >>= 1) {
        s    += __shfl_xor_sync(0xffffffffu, s, off);
        acc0 += __shfl_xor_sync(0xffffffffu, acc0, off);
        acc1 += __shfl_xor_sync(0xffffffffu, acc1, off);
    }
    if (lane == 0) {
        float inv = 1.0f / (s + 1e-16f);
        *(float2*)(out + (size_t)g * 2) =
            make_float2(acc0 * inv + __ldg(&bias[0]), acc1 * inv + __ldg(&bias[1]));
    }
}

__global__ void agg2_all(
    const int* __restrict__ cnt_ub, const int* __restrict__ bkt_ub,
    const float* __restrict__ ad2b, const float* __restrict__ hs2u,
    const float* __restrict__ a2ubs, const float* __restrict__ b2ub,
    float* __restrict__ out_b,
    const int* __restrict__ cnt_bu, const int* __restrict__ bkt_bu,
    const float* __restrict__ ad2u, const float* __restrict__ hs2b,
    const float* __restrict__ a2bus, const float* __restrict__ b2bu,
    float* __restrict__ out_u) {
    int w = blockIdx.x * (blockDim.x >> 5) + (threadIdx.x >> 5);
    int wl = threadIdx.x & 31;
    if (w < NB) {
        agg2_grp<32, STRIDE_B>(w, wl, cnt_ub, bkt_ub, ad2b, hs2u, a2ubs, b2ub, out_b);
    } else {
        int g = (w - NB) * 4 + (wl >> 3);
        if (g < NU)
            agg2_grp<8, STRIDE_U>(g, wl & 7, cnt_bu, bkt_bu, ad2u, hs2b, a2bus, b2bu, out_u);
    }
}

// ---------------- host ----------------
static void* sym_addr(const void* symbol) {
    void* p = nullptr;
    cudaGetSymbolAddress(&p, symbol);
    return p;
}

extern "C" void kernel_launch(void* const* d_in, const int* in_sizes, int n_in,
                              void* d_out, int out_size) {
    const float* x_user  = (const float*)d_in[0];
    const float* x_badge = (const float*)d_in[1];
    const int* ub_src = (const int*)d_in[2];
    const int* ub_dst = (const int*)d_in[3];
    const int* bu_src = (const int*)d_in[4];
    const int* bu_dst = (const int*)d_in[5];

    int iW1ubs = 8, iW1ubd = 9, ia1ubs = 10, ia1ubd = 11, ib1ub = 12;
    int iW1bus, iW1bud, ia1bus, ia1bud, ib1bu;
    int iW2ubs, iW2ubd, ia2ubs, ia2ubd, ib2ub;
    int iW2bus, iW2bud, ia2bus, ia2bud, ib2bu;
    if (in_sizes[13] == 1024) {
        iW1bus = 13; iW1bud = 14; ia1bus = 15; ia1bud = 16; ib1bu = 17;
        iW2ubs = 18; iW2ubd = 19; ia2ubs = 20; ia2ubd = 21; ib2ub = 22;
        iW2bus = 23; iW2bud = 24; ia2bus = 25; ia2bud = 26; ib2bu = 27;
    } else {
        iW2ubs = 13; iW2ubd = 14; ia2ubs = 15; ia2ubd = 16; ib2ub = 17;
        iW1bus = 18; iW1bud = 19; ia1bus = 20; ia1bud = 21; ib1bu = 22;
        iW2bus = 23; iW2bud = 24; ia2bus = 25; ia2bud = 26; ib2bu = 27;
    }
#define FP(i) ((const float*)d_in[i])

    int* cnt     = (int*)sym_addr(g_cnt);
    int* cnt_bu  = cnt;
    int* cnt_ub  = cnt + NU;
    int* bkt_ub  = (int*)sym_addr(g_bkt_ub);
    int* bkt_bu  = (int*)sym_addr(g_bkt_bu);
    uint4* hs1u = (uint4*)sym_addr(g_hs1_u);
    uint4* hs1b = (uint4*)sym_addr(g_hs1_b);
    float* ad1u = (float*)sym_addr(g_ad1_u);
    float* ad1b = (float*)sym_addr(g_ad1_b);
    float* hs2u = (float*)sym_addr(g_hs2_u);
    float* hs2b = (float*)sym_addr(g_hs2_b);
    float* ad2u = (float*)sym_addr(g_ad2_u);
    float* ad2b = (float*)sym_addr(g_ad2_b);

    // ---- bucket build + layer-1 node transforms (one fused, interleaved launch) ----
    cudaMemsetAsync(cnt, 0, (NU + NB) * sizeof(int));
    build_node_kernel<<<TOTAL_BLOCKS, 256>>>(
        ub_src, ub_dst, cnt_ub, bkt_ub,
        bu_src, bu_dst, cnt_bu, bkt_bu,
        x_user, x_badge,
        FP(iW1ubs), FP(iW1bud), FP(ia1bud),
        FP(iW1bus), FP(iW1ubd), FP(ia1ubd),
        hs1u, ad1u, hs1b, ad1b);

    // ---- layer 1 aggregation + fused layer-2 node transform (one launch) ----
    {
        long warps = (long)NB + (NU + 3) / 4;
        int blocks = (int)((warps * 32 + 255) / 256);
        agg1_all<<<blocks, 256>>>(
            cnt_ub, bkt_ub, ad1b, hs1u, FP(ia1ubs), FP(ib1ub),
            FP(iW2bus), FP(iW2ubd), FP(ia2ubd), hs2b, ad2b,
            cnt_bu, bkt_bu, ad1u, hs1b, FP(ia1bus), FP(ib1bu),
            FP(iW2ubs), FP(iW2bud), FP(ia2bud), hs2u, ad2u);
    }

    // ---- layer 2 aggregation -> outputs (one launch) ----
    float* out = (float*)d_out;   // [ou (200000x2) | ob (50000x2)]
    {
        long warps = (long)NB + (NU + 3) / 4;
        int blocks = (int)((warps * 32 + 255) / 256);
        agg2_all<<<blocks, 256>>>(
            cnt_ub, bkt_ub, ad2b, hs2u, FP(ia2ubs), FP(ib2ub), out + (size_t)NU * 2,
            cnt_bu, bkt_bu, ad2u, hs2b, FP(ia2bus), FP(ib2bu), out);
    }
}

// round 15
// speedup vs baseline: 1.2624x; 1.0048x over previous
#include <cuda_runtime.h>
#include <cuda_fp16.h>
#include <math.h>

#define NU 200000
#define NB 50000
#define NE 5000000
#define STRIDE_B 192
#define STRIDE_U 64

// ---------------- scratch ----------------
__device__ int g_cnt[NU + NB];   // zero at module load; agg2 re-zeroes after use
__device__ int g_bkt_ub[(size_t)NB * STRIDE_B];
__device__ int g_bkt_bu[(size_t)NU * STRIDE_U];

__device__ uint4 g_hs1_u[NU * 2];         // fp16 rows: 16 halves = 32B
__device__ uint4 g_hs1_b[NB * 2];
__device__ float g_ad1_u[NU];
__device__ float g_ad1_b[NB];
__device__ float g_hs2_u[NU * 2], g_hs2_b[NB * 2];
__device__ float g_ad2_u[NU];
__device__ float g_ad2_b[NB];

#define GE8_BLOCKS ((NE / 8 + 255) / 256)          // 2442
#define UBLK ((NU + 255) / 256)                     // 782
#define BBLK ((NB + 255) / 256)                     // 196
#define NODE_BLOCKS (UBLK + BBLK)                   // 978
// interleave: per 7-block group, 5 build + 2 node
#define NGROUPS ((GE8_BLOCKS + 4) / 5)              // 489
#define TOTAL_BLOCKS (NGROUPS * 7)                  // 3423

// ---------------- fused build + node transform, interleaved (R14 bodies) ----------
__global__ void build_node_kernel(
    const int* __restrict__ ub_src, const int* __restrict__ ub_dst,
    int* __restrict__ cnt_ub, int* __restrict__ bkt_ub,
    const int* __restrict__ bu_src, const int* __restrict__ bu_dst,
    int* __restrict__ cnt_bu, int* __restrict__ bkt_bu,
    const float* __restrict__ xu, const float* __restrict__ xb,
    const float* __restrict__ Ws_u, const float* __restrict__ Wd_u,
    const float* __restrict__ avd_u,
    const float* __restrict__ Ws_b, const float* __restrict__ Wd_b,
    const float* __restrict__ avd_b,
    uint4* __restrict__ hs_u, float* __restrict__ ad_u,
    uint4* __restrict__ hs_b, float* __restrict__ ad_b) {
    __shared__ float sWs[64 * 16], swd[64];

    int grp = blockIdx.x / 7;
    int sub = blockIdx.x % 7;
    bool isBuild = (sub < 5);
    int bid = isBuild ? (grp * 5 + sub) : (grp * 2 + (sub - 5));

    if (isBuild) {
        if (bid >= GE8_BLOCKS) return;
        int t = bid * 256 + threadIdx.x;
        if (t >= NE / 8) return;
        // streaming loads: edge indices are single-use (evict-first)
        int4 da0 = __ldcs((const int4*)ub_dst + 2 * t + 0);
        int4 da1 = __ldcs((const int4*)ub_dst + 2 * t + 1);
        int4 db0 = __ldcs((const int4*)bu_dst + 2 * t + 0);
        int4 db1 = __ldcs((const int4*)bu_dst + 2 * t + 1);
        int4 sa0 = __ldcs((const int4*)ub_src + 2 * t + 0);
        int4 sa1 = __ldcs((const int4*)ub_src + 2 * t + 1);
        int4 sb0 = __ldcs((const int4*)bu_src + 2 * t + 0);
        int4 sb1 = __ldcs((const int4*)bu_src + 2 * t + 1);

        int r0 = atomicAdd(&cnt_ub[da0.x], 1);
        int r1 = atomicAdd(&cnt_ub[da0.y], 1);
        int r2 = atomicAdd(&cnt_ub[da0.z], 1);
        int r3 = atomicAdd(&cnt_ub[da0.w], 1);
        int r4 = atomicAdd(&cnt_ub[da1.x], 1);
        int r5 = atomicAdd(&cnt_ub[da1.y], 1);
        int r6 = atomicAdd(&cnt_ub[da1.z], 1);
        int r7 = atomicAdd(&cnt_ub[da1.w], 1);
        int q0 = atomicAdd(&cnt_bu[db0.x], 1);
        int q1 = atomicAdd(&cnt_bu[db0.y], 1);
        int q2 = atomicAdd(&cnt_bu[db0.z], 1);
        int q3 = atomicAdd(&cnt_bu[db0.w], 1);
        int q4 = atomicAdd(&cnt_bu[db1.x], 1);
        int q5 = atomicAdd(&cnt_bu[db1.y], 1);
        int q6 = atomicAdd(&cnt_bu[db1.z], 1);
        int q7 = atomicAdd(&cnt_bu[db1.w], 1);

        if (r0 < STRIDE_B) bkt_ub[(size_t)da0.x * STRIDE_B + r0] = sa0.x;
        if (r1 < STRIDE_B) bkt_ub[(size_t)da0.y * STRIDE_B + r1] = sa0.y;
        if (r2 < STRIDE_B) bkt_ub[(size_t)da0.z * STRIDE_B + r2] = sa0.z;
        if (r3 < STRIDE_B) bkt_ub[(size_t)da0.w * STRIDE_B + r3] = sa0.w;
        if (r4 < STRIDE_B) bkt_ub[(size_t)da1.x * STRIDE_B + r4] = sa1.x;
        if (r5 < STRIDE_B) bkt_ub[(size_t)da1.y * STRIDE_B + r5] = sa1.y;
        if (r6 < STRIDE_B) bkt_ub[(size_t)da1.z * STRIDE_B + r6] = sa1.z;
        if (r7 < STRIDE_B) bkt_ub[(size_t)da1.w * STRIDE_B + r7] = sa1.w;
        if (q0 < STRIDE_U) bkt_bu[(size_t)db0.x * STRIDE_U + q0] = sb0.x;
        if (q1 < STRIDE_U) bkt_bu[(size_t)db0.y * STRIDE_U + q1] = sb0.y;
        if (q2 < STRIDE_U) bkt_bu[(size_t)db0.z * STRIDE_U + q2] = sb0.z;
        if (q3 < STRIDE_U) bkt_bu[(size_t)db0.w * STRIDE_U + q3] = sb0.w;
        if (q4 < STRIDE_U) bkt_bu[(size_t)db1.x * STRIDE_U + q4] = sb1.x;
        if (q5 < STRIDE_U) bkt_bu[(size_t)db1.y * STRIDE_U + q5] = sb1.y;
        if (q6 < STRIDE_U) bkt_bu[(size_t)db1.z * STRIDE_U + q6] = sb1.z;
        if (q7 < STRIDE_U) bkt_bu[(size_t)db1.w * STRIDE_U + q7] = sb1.w;
        return;
    }

    // ---------- node transform (hd eliminated via wdvec = Wd @ avd) ----------
    if (bid >= NODE_BLOCKS) return;
    bool isU = (bid < UBLK);
    const float* x   = isU ? xu : xb;
    const float* Ws  = isU ? Ws_u : Ws_b;
    const float* Wd  = isU ? Wd_u : Wd_b;
    const float* avd = isU ? avd_u : avd_b;
    uint4* hso       = isU ? hs_u : hs_b;
    float* ado       = isU ? ad_u : ad_b;
    int n            = isU ? NU : NB;
    int i = (isU ? bid : bid - UBLK) * 256 + threadIdx.x;

    for (int j = threadIdx.x; j < 1024; j += 256) sWs[j] = Ws[j];
    if (threadIdx.x < 64) {
        float acc = 0.f;
#pragma unroll
        for (int c = 0; c < 16; c++) acc += Wd[threadIdx.x * 16 + c] * avd[c];
        swd[threadIdx.x] = acc;
    }
    __syncthreads();
    if (i >= n) return;

    float hs[16];
#pragma unroll
    for (int c = 0; c < 16; c++) hs[c] = 0.f;
    float ad = 0.f;
    const float4* xp = (const float4*)(x + (size_t)i * 64);
#pragma unroll 4
    for (int q = 0; q < 16; q++) {
        float4 v = __ldcs(xp + q);   // x rows are single-use: evict-first
#pragma unroll
        for (int kk = 0; kk < 4; kk++) {
            float xk = (kk == 0) ? v.x : (kk == 1) ? v.y : (kk == 2) ? v.z : v.w;
            int k = q * 4 + kk;
#pragma unroll
            for (int c = 0; c < 16; c++) hs[c] += xk * sWs[k * 16 + c];
            ad += xk * swd[k];
        }
    }
    __half2 h2[8];
#pragma unroll
    for (int q = 0; q < 8; q++)
        h2[q] = __floats2half2_rn(hs[2 * q + 0], hs[2 * q + 1]);
    uint4 o0, o1;
    o0.x = *(unsigned int*)&h2[0]; o0.y = *(unsigned int*)&h2[1];
    o0.z = *(unsigned int*)&h2[2]; o0.w = *(unsigned int*)&h2[3];
    o1.x = *(unsigned int*)&h2[4]; o1.y = *(unsigned int*)&h2[5];
    o1.z = *(unsigned int*)&h2[6]; o1.w = *(unsigned int*)&h2[7];
    hso[(size_t)i * 2 + 0] = o0;
    hso[(size_t)i * 2 + 1] = o1;
    ado[i] = ad;
}

// ---------------- layer-1 aggregation (per-lane gather) + fused L2 transform ----------
template <int G, int STRIDE>
__device__ __forceinline__ void agg1_grp(
    int g, int lane,
    const int* __restrict__ cnt, const int* __restrict__ bkt,
    const float* __restrict__ ad_, const uint4* __restrict__ hs,
    const float* __restrict__ avec, const float* __restrict__ bias,
    const float* __restrict__ W2s, const float* __restrict__ W2d,
    const float* __restrict__ a2d,
    float* __restrict__ hs2_out, float* __restrict__ ad2_out) {
    float a[16];
#pragma unroll
    for (int c = 0; c < 16; c++) a[c] = __ldg(&avec[c]);
    float adv = __ldg(&ad_[g]);
    int deg = __ldg(&cnt[g]);
    if (deg > STRIDE) deg = STRIDE;
    const int* row = bkt + (size_t)g * STRIDE;

    float s = 0.f;
    float acc[16];
#pragma unroll
    for (int c = 0; c < 16; c++) acc[c] = 0.f;

    int i = lane;
    int src = (i < deg) ? __ldg(&row[i]) : 0;
    while (i < deg) {
        int inext = i + G;
        int src_next = (inext < deg) ? __ldg(&row[inext]) : 0;
        uint4 v0 = __ldg(&hs[(size_t)src * 2 + 0]);
        uint4 v1 = __ldg(&hs[(size_t)src * 2 + 1]);
        unsigned int w32[8] = {v0.x, v0.y, v0.z, v0.w, v1.x, v1.y, v1.z, v1.w};
        float h[16];
#pragma unroll
        for (int q = 0; q < 8; q++) {
            float2 f = __half22float2(*(__half2*)&w32[q]);
            h[2 * q + 0] = f.x;
            h[2 * q + 1] = f.y;
        }
        float es = 0.f;
#pragma unroll
        for (int c = 0; c < 16; c++) es += h[c] * a[c];
        float e = es + adv;
        e = (e > 0.f) ? e : 0.2f * e;
        float w = __expf(e);
        s += w;
#pragma unroll
        for (int c = 0; c < 16; c++) acc[c] += w * h[c];
        src = src_next;
        i = inext;
    }

#pragma unroll
    for (int off = G / 2; off; off >>= 1) {
        s += __shfl_xor_sync(0xffffffffu, s, off);
#pragma unroll
        for (int c = 0; c < 16; c++)
            acc[c] += __shfl_xor_sync(0xffffffffu, acc[c], off);
    }

    if (lane == 0) {
        float inv = 1.0f / (s + 1e-16f);
        float s0 = 0.f, s1 = 0.f, d0 = 0.f, d1 = 0.f;
#pragma unroll
        for (int c = 0; c < 16; c++) {
            float h = fmaxf(acc[c] * inv + __ldg(&bias[c]), 0.f);
            s0 += h * __ldg(&W2s[c * 2 + 0]);
            s1 += h * __ldg(&W2s[c * 2 + 1]);
            d0 += h * __ldg(&W2d[c * 2 + 0]);
            d1 += h * __ldg(&W2d[c * 2 + 1]);
        }
        *(float2*)(hs2_out + (size_t)g * 2) = make_float2(s0, s1);
        ad2_out[g] = d0 * __ldg(&a2d[0]) + d1 * __ldg(&a2d[1]);
    }
}

__global__ void agg1_all(
    const int* __restrict__ cnt_ub, const int* __restrict__ bkt_ub,
    const float* __restrict__ ad1b, const uint4* __restrict__ hs1u,
    const float* __restrict__ a1ubs, const float* __restrict__ b1ub,
    const float* __restrict__ W2bus, const float* __restrict__ W2ubd,
    const float* __restrict__ a2ubd,
    float* __restrict__ hs2b, float* __restrict__ ad2b,
    const int* __restrict__ cnt_bu, const int* __restrict__ bkt_bu,
    const float* __restrict__ ad1u, const uint4* __restrict__ hs1b,
    const float* __restrict__ a1bus, const float* __restrict__ b1bu,
    const float* __restrict__ W2ubs, const float* __restrict__ W2bud,
    const float* __restrict__ a2bud,
    float* __restrict__ hs2u, float* __restrict__ ad2u) {
    int w = blockIdx.x * (blockDim.x >> 5) + (threadIdx.x >> 5);
    int wl = threadIdx.x & 31;
    if (w < NB) {
        agg1_grp<32, STRIDE_B>(w, wl, cnt_ub, bkt_ub, ad1b, hs1u, a1ubs, b1ub,
                               W2bus, W2ubd, a2ubd, hs2b, ad2b);
    } else {
        int g = (w - NB) * 4 + (wl >> 3);     // 4 user dsts per warp, G=8
        if (g < NU)
            agg1_grp<8, STRIDE_U>(g, wl & 7, cnt_bu, bkt_bu, ad1u, hs1b, a1bus, b1bu,
                                  W2ubs, W2bud, a2bud, hs2u, ad2u);
    }
}

// ---------------- layer-2 aggregation (merged relations; clears cnt after use) ----------
template <int G, int STRIDE>
__device__ __forceinline__ void agg2_grp(int g, int lane,
                                         int* __restrict__ cnt, const int* __restrict__ bkt,
                                         const float* __restrict__ ad_, const float* __restrict__ hs,
                                         const float* __restrict__ avec, const float* __restrict__ bias,
                                         float* __restrict__ out) {
    float a0 = __ldg(&avec[0]), a1 = __ldg(&avec[1]);
    float adv = __ldg(&ad_[g]);
    int deg = cnt[g];
    if (lane == 0) cnt[g] = 0;   // self-clear: next replay starts from zeros (no memset)
    if (deg > STRIDE) deg = STRIDE;
    const int* row = bkt + (size_t)g * STRIDE;

    float s = 0.f, acc0 = 0.f, acc1 = 0.f;
    int i = lane;
    int src = (i < deg) ? __ldg(&row[i]) : 0;
    while (i < deg) {
        int inext = i + G;
        int src_next = (inext < deg) ? __ldg(&row[inext]) : 0;
        float2 v = *(const float2*)(hs + (size_t)src * 2);
        float e = v.x * a0 + v.y * a1 + adv;
        e = (e > 0.f) ? e : 0.2f * e;
        float w = __expf(e);
        s += w;
        acc0 += w * v.x;
        acc1 += w * v.y;
        src = src_next;
        i = inext;
    }
#pragma unroll
    for (int off = G / 2; off; off >>= 1) {
        s    += __shfl_xor_sync(0xffffffffu, s, off);
        acc0 += __shfl_xor_sync(0xffffffffu, acc0, off);
        acc1 += __shfl_xor_sync(0xffffffffu, acc1, off);
    }
    if (lane == 0) {
        float inv = 1.0f / (s + 1e-16f);
        *(float2*)(out + (size_t)g * 2) =
            make_float2(acc0 * inv + __ldg(&bias[0]), acc1 * inv + __ldg(&bias[1]));
    }
}

__global__ void agg2_all(
    int* __restrict__ cnt_ub, const int* __restrict__ bkt_ub,
    const float* __restrict__ ad2b, const float* __restrict__ hs2u,
    const float* __restrict__ a2ubs, const float* __restrict__ b2ub,
    float* __restrict__ out_b,
    int* __restrict__ cnt_bu, const int* __restrict__ bkt_bu,
    const float* __restrict__ ad2u, const float* __restrict__ hs2b,
    const float* __restrict__ a2bus, const float* __restrict__ b2bu,
    float* __restrict__ out_u) {
    int w = blockIdx.x * (blockDim.x >> 5) + (threadIdx.x >> 5);
    int wl = threadIdx.x & 31;
    if (w < NB) {
        agg2_grp<32, STRIDE_B>(w, wl, cnt_ub, bkt_ub, ad2b, hs2u, a2ubs, b2ub, out_b);
    } else {
        int g = (w - NB) * 4 + (wl >> 3);
        if (g < NU)
            agg2_grp<8, STRIDE_U>(g, wl & 7, cnt_bu, bkt_bu, ad2u, hs2b, a2bus, b2bu, out_u);
    }
}

// ---------------- host ----------------
static void* sym_addr(const void* symbol) {
    void* p = nullptr;
    cudaGetSymbolAddress(&p, symbol);
    return p;
}

extern "C" void kernel_launch(void* const* d_in, const int* in_sizes, int n_in,
                              void* d_out, int out_size) {
    const float* x_user  = (const float*)d_in[0];
    const float* x_badge = (const float*)d_in[1];
    const int* ub_src = (const int*)d_in[2];
    const int* ub_dst = (const int*)d_in[3];
    const int* bu_src = (const int*)d_in[4];
    const int* bu_dst = (const int*)d_in[5];

    int iW1ubs = 8, iW1ubd = 9, ia1ubs = 10, ia1ubd = 11, ib1ub = 12;
    int iW1bus, iW1bud, ia1bus, ia1bud, ib1bu;
    int iW2ubs, iW2ubd, ia2ubs, ia2ubd, ib2ub;
    int iW2bus, iW2bud, ia2bus, ia2bud, ib2bu;
    if (in_sizes[13] == 1024) {
        iW1bus = 13; iW1bud = 14; ia1bus = 15; ia1bud = 16; ib1bu = 17;
        iW2ubs = 18; iW2ubd = 19; ia2ubs = 20; ia2ubd = 21; ib2ub = 22;
        iW2bus = 23; iW2bud = 24; ia2bus = 25; ia2bud = 26; ib2bu = 27;
    } else {
        iW2ubs = 13; iW2ubd = 14; ia2ubs = 15; ia2ubd = 16; ib2ub = 17;
        iW1bus = 18; iW1bud = 19; ia1bus = 20; ia1bud = 21; ib1bu = 22;
        iW2bus = 23; iW2bud = 24; ia2bus = 25; ia2bud = 26; ib2bu = 27;
    }
#define FP(i) ((const float*)d_in[i])

    int* cnt     = (int*)sym_addr(g_cnt);
    int* cnt_bu  = cnt;
    int* cnt_ub  = cnt + NU;
    int* bkt_ub  = (int*)sym_addr(g_bkt_ub);
    int* bkt_bu  = (int*)sym_addr(g_bkt_bu);
    uint4* hs1u = (uint4*)sym_addr(g_hs1_u);
    uint4* hs1b = (uint4*)sym_addr(g_hs1_b);
    float* ad1u = (float*)sym_addr(g_ad1_u);
    float* ad1b = (float*)sym_addr(g_ad1_b);
    float* hs2u = (float*)sym_addr(g_hs2_u);
    float* hs2b = (float*)sym_addr(g_hs2_b);
    float* ad2u = (float*)sym_addr(g_ad2_u);
    float* ad2b = (float*)sym_addr(g_ad2_b);

    // ---- bucket build + layer-1 node transforms (one fused, interleaved launch) ----
    // (no memset: g_cnt is zero at load and agg2 re-zeroes it each run)
    build_node_kernel<<<TOTAL_BLOCKS, 256>>>(
        ub_src, ub_dst, cnt_ub, bkt_ub,
        bu_src, bu_dst, cnt_bu, bkt_bu,
        x_user, x_badge,
        FP(iW1ubs), FP(iW1bud), FP(ia1bud),
        FP(iW1bus), FP(iW1ubd), FP(ia1ubd),
        hs1u, ad1u, hs1b, ad1b);

    // ---- layer 1 aggregation + fused layer-2 node transform (one launch) ----
    {
        long warps = (long)NB + (NU + 3) / 4;
        int blocks = (int)((warps * 32 + 255) / 256);
        agg1_all<<<blocks, 256>>>(
            cnt_ub, bkt_ub, ad1b, hs1u, FP(ia1ubs), FP(ib1ub),
            FP(iW2bus), FP(iW2ubd), FP(ia2ubd), hs2b, ad2b,
            cnt_bu, bkt_bu, ad1u, hs1b, FP(ia1bus), FP(ib1bu),
            FP(iW2ubs), FP(iW2bud), FP(ia2bud), hs2u, ad2u);
    }

    // ---- layer 2 aggregation -> outputs (one launch; clears cnt for next replay) ----
    float* out = (float*)d_out;   // [ou (200000x2) | ob (50000x2)]
    {
        long warps = (long)NB + (NU + 3) / 4;
        int blocks = (int)((warps * 32 + 255) / 256);
        agg2_all<<<blocks, 256>>>(
            cnt_ub, bkt_ub, ad2b, hs2u, FP(ia2ubs), FP(ib2ub), out + (size_t)NU * 2,
            cnt_bu, bkt_bu, ad2u, hs2b, FP(ia2bus), FP(ib2bu), out);
    }
}

// round 16
// speedup vs baseline: 1.3204x; 1.0460x over previous
#include <cuda_runtime.h>
#include <cuda_fp16.h>
#include <math.h>

#define NU 200000
#define NB 50000
#define NE 5000000
#define STRIDE_B 192
#define STRIDE_U 64

// ---------------- scratch ----------------
__device__ int g_cnt[NU + NB];   // zero at module load; agg2 re-zeroes after use
__device__ int g_bkt_ub[(size_t)NB * STRIDE_B];
__device__ int g_bkt_bu[(size_t)NU * STRIDE_U];

__device__ uint4 g_hs1_u[NU * 2];         // fp16 rows: 16 halves = 32B
__device__ uint4 g_hs1_b[NB * 2];
__device__ float g_ad1_u[NU];
__device__ float g_ad1_b[NB];
__device__ float g_hs2_u[NU * 2], g_hs2_b[NB * 2];
__device__ float g_ad2_u[NU];
__device__ float g_ad2_b[NB];

#define GE8_BLOCKS ((NE / 8 + 255) / 256)          // 2442
#define UBLK ((NU + 255) / 256)                     // 782
#define BBLK ((NB + 255) / 256)                     // 196
#define NODE_BLOCKS (UBLK + BBLK)                   // 978
#define NGROUPS ((GE8_BLOCKS + 4) / 5)              // 489
#define TOTAL_BLOCKS (NGROUPS * 7)                  // 3423

// ---------------- fused build + node transform, interleaved (R15 exact) ----------
__global__ void build_node_kernel(
    const int* __restrict__ ub_src, const int* __restrict__ ub_dst,
    int* __restrict__ cnt_ub, int* __restrict__ bkt_ub,
    const int* __restrict__ bu_src, const int* __restrict__ bu_dst,
    int* __restrict__ cnt_bu, int* __restrict__ bkt_bu,
    const float* __restrict__ xu, const float* __restrict__ xb,
    const float* __restrict__ Ws_u, const float* __restrict__ Wd_u,
    const float* __restrict__ avd_u,
    const float* __restrict__ Ws_b, const float* __restrict__ Wd_b,
    const float* __restrict__ avd_b,
    uint4* __restrict__ hs_u, float* __restrict__ ad_u,
    uint4* __restrict__ hs_b, float* __restrict__ ad_b) {
    __shared__ float sWs[64 * 16], swd[64];

    int grp = blockIdx.x / 7;
    int sub = blockIdx.x % 7;
    bool isBuild = (sub < 5);
    int bid = isBuild ? (grp * 5 + sub) : (grp * 2 + (sub - 5));

    if (isBuild) {
        if (bid >= GE8_BLOCKS) return;
        int t = bid * 256 + threadIdx.x;
        if (t >= NE / 8) return;
        int4 da0 = __ldcs((const int4*)ub_dst + 2 * t + 0);
        int4 da1 = __ldcs((const int4*)ub_dst + 2 * t + 1);
        int4 db0 = __ldcs((const int4*)bu_dst + 2 * t + 0);
        int4 db1 = __ldcs((const int4*)bu_dst + 2 * t + 1);
        int4 sa0 = __ldcs((const int4*)ub_src + 2 * t + 0);
        int4 sa1 = __ldcs((const int4*)ub_src + 2 * t + 1);
        int4 sb0 = __ldcs((const int4*)bu_src + 2 * t + 0);
        int4 sb1 = __ldcs((const int4*)bu_src + 2 * t + 1);

        int r0 = atomicAdd(&cnt_ub[da0.x], 1);
        int r1 = atomicAdd(&cnt_ub[da0.y], 1);
        int r2 = atomicAdd(&cnt_ub[da0.z], 1);
        int r3 = atomicAdd(&cnt_ub[da0.w], 1);
        int r4 = atomicAdd(&cnt_ub[da1.x], 1);
        int r5 = atomicAdd(&cnt_ub[da1.y], 1);
        int r6 = atomicAdd(&cnt_ub[da1.z], 1);
        int r7 = atomicAdd(&cnt_ub[da1.w], 1);
        int q0 = atomicAdd(&cnt_bu[db0.x], 1);
        int q1 = atomicAdd(&cnt_bu[db0.y], 1);
        int q2 = atomicAdd(&cnt_bu[db0.z], 1);
        int q3 = atomicAdd(&cnt_bu[db0.w], 1);
        int q4 = atomicAdd(&cnt_bu[db1.x], 1);
        int q5 = atomicAdd(&cnt_bu[db1.y], 1);
        int q6 = atomicAdd(&cnt_bu[db1.z], 1);
        int q7 = atomicAdd(&cnt_bu[db1.w], 1);

        if (r0 < STRIDE_B) bkt_ub[(size_t)da0.x * STRIDE_B + r0] = sa0.x;
        if (r1 < STRIDE_B) bkt_ub[(size_t)da0.y * STRIDE_B + r1] = sa0.y;
        if (r2 < STRIDE_B) bkt_ub[(size_t)da0.z * STRIDE_B + r2] = sa0.z;
        if (r3 < STRIDE_B) bkt_ub[(size_t)da0.w * STRIDE_B + r3] = sa0.w;
        if (r4 < STRIDE_B) bkt_ub[(size_t)da1.x * STRIDE_B + r4] = sa1.x;
        if (r5 < STRIDE_B) bkt_ub[(size_t)da1.y * STRIDE_B + r5] = sa1.y;
        if (r6 < STRIDE_B) bkt_ub[(size_t)da1.z * STRIDE_B + r6] = sa1.z;
        if (r7 < STRIDE_B) bkt_ub[(size_t)da1.w * STRIDE_B + r7] = sa1.w;
        if (q0 < STRIDE_U) bkt_bu[(size_t)db0.x * STRIDE_U + q0] = sb0.x;
        if (q1 < STRIDE_U) bkt_bu[(size_t)db0.y * STRIDE_U + q1] = sb0.y;
        if (q2 < STRIDE_U) bkt_bu[(size_t)db0.z * STRIDE_U + q2] = sb0.z;
        if (q3 < STRIDE_U) bkt_bu[(size_t)db0.w * STRIDE_U + q3] = sb0.w;
        if (q4 < STRIDE_U) bkt_bu[(size_t)db1.x * STRIDE_U + q4] = sb1.x;
        if (q5 < STRIDE_U) bkt_bu[(size_t)db1.y * STRIDE_U + q5] = sb1.y;
        if (q6 < STRIDE_U) bkt_bu[(size_t)db1.z * STRIDE_U + q6] = sb1.z;
        if (q7 < STRIDE_U) bkt_bu[(size_t)db1.w * STRIDE_U + q7] = sb1.w;
        return;
    }

    if (bid >= NODE_BLOCKS) return;
    bool isU = (bid < UBLK);
    const float* x   = isU ? xu : xb;
    const float* Ws  = isU ? Ws_u : Ws_b;
    const float* Wd  = isU ? Wd_u : Wd_b;
    const float* avd = isU ? avd_u : avd_b;
    uint4* hso       = isU ? hs_u : hs_b;
    float* ado       = isU ? ad_u : ad_b;
    int n            = isU ? NU : NB;
    int i = (isU ? bid : bid - UBLK) * 256 + threadIdx.x;

    for (int j = threadIdx.x; j < 1024; j += 256) sWs[j] = Ws[j];
    if (threadIdx.x < 64) {
        float acc = 0.f;
#pragma unroll
        for (int c = 0; c < 16; c++) acc += Wd[threadIdx.x * 16 + c] * avd[c];
        swd[threadIdx.x] = acc;
    }
    __syncthreads();
    if (i >= n) return;

    float hs[16];
#pragma unroll
    for (int c = 0; c < 16; c++) hs[c] = 0.f;
    float ad = 0.f;
    const float4* xp = (const float4*)(x + (size_t)i * 64);
#pragma unroll 4
    for (int q = 0; q < 16; q++) {
        float4 v = __ldcs(xp + q);
#pragma unroll
        for (int kk = 0; kk < 4; kk++) {
            float xk = (kk == 0) ? v.x : (kk == 1) ? v.y : (kk == 2) ? v.z : v.w;
            int k = q * 4 + kk;
#pragma unroll
            for (int c = 0; c < 16; c++) hs[c] += xk * sWs[k * 16 + c];
            ad += xk * swd[k];
        }
    }
    __half2 h2[8];
#pragma unroll
    for (int q = 0; q < 8; q++)
        h2[q] = __floats2half2_rn(hs[2 * q + 0], hs[2 * q + 1]);
    uint4 o0, o1;
    o0.x = *(unsigned int*)&h2[0]; o0.y = *(unsigned int*)&h2[1];
    o0.z = *(unsigned int*)&h2[2]; o0.w = *(unsigned int*)&h2[3];
    o1.x = *(unsigned int*)&h2[4]; o1.y = *(unsigned int*)&h2[5];
    o1.z = *(unsigned int*)&h2[6]; o1.w = *(unsigned int*)&h2[7];
    hso[(size_t)i * 2 + 0] = o0;
    hso[(size_t)i * 2 + 1] = o1;
    ado[i] = ad;
}

// ---------------- agg1 badge: PAIR-cooperative gather (1 wavefront/edge) ----------
// 2 lanes per edge; lane h loads 16B half of the 32B row (same 128B line as its
// partner -> halved L1 wavefronts). Both shuffles issued before both LDGs (MLP).
// Both lanes hold identical w/s copies; reduction over pair-strides only (xor
// 2,4,8,16) counts each edge exactly once.
__device__ __forceinline__ void agg1_pair_badge(
    int g, int lane,
    const int* __restrict__ cnt, const int* __restrict__ bkt,
    const float* __restrict__ ad_, const uint4* __restrict__ hs,
    const float* __restrict__ avec, const float* __restrict__ bias,
    const float* __restrict__ W2s, const float* __restrict__ W2d,
    const float* __restrict__ a2d,
    float* __restrict__ hs2_out, float* __restrict__ ad2_out) {
    int p = lane >> 1;       // pair id 0..15
    int h = lane & 1;        // half: channels h*8 .. h*8+7

    float a[8];
#pragma unroll
    for (int c = 0; c < 8; c++) a[c] = __ldg(&avec[h * 8 + c]);
    float adv = __ldg(&ad_[g]);
    int deg = __ldg(&cnt[g]);
    if (deg > STRIDE_B) deg = STRIDE_B;
    const int* row = bkt + (size_t)g * STRIDE_B;

    float s = 0.f;
    float acc[8];
#pragma unroll
    for (int c = 0; c < 8; c++) acc[c] = 0.f;

    for (int c0 = 0; c0 < deg; c0 += 32) {
        int sidx = (c0 + lane < deg) ? __ldg(&row[c0 + lane]) : 0;
        int kmax = deg - c0;
        int src0 = __shfl_sync(0xffffffffu, sidx, p);
        int src1 = __shfl_sync(0xffffffffu, sidx, 16 + p);
        bool v0 = (p < kmax);
        bool v1 = (16 + p < kmax);
        uint4 r0 = make_uint4(0u, 0u, 0u, 0u), r1 = make_uint4(0u, 0u, 0u, 0u);
        if (v0) r0 = __ldg(&hs[(size_t)src0 * 2 + h]);
        if (v1) r1 = __ldg(&hs[(size_t)src1 * 2 + h]);

        float h0[8], h1[8];
        {
            float2 f;
            f = __half22float2(*(__half2*)&r0.x); h0[0] = f.x; h0[1] = f.y;
            f = __half22float2(*(__half2*)&r0.y); h0[2] = f.x; h0[3] = f.y;
            f = __half22float2(*(__half2*)&r0.z); h0[4] = f.x; h0[5] = f.y;
            f = __half22float2(*(__half2*)&r0.w); h0[6] = f.x; h0[7] = f.y;
            f = __half22float2(*(__half2*)&r1.x); h1[0] = f.x; h1[1] = f.y;
            f = __half22float2(*(__half2*)&r1.y); h1[2] = f.x; h1[3] = f.y;
            f = __half22float2(*(__half2*)&r1.z); h1[4] = f.x; h1[5] = f.y;
            f = __half22float2(*(__half2*)&r1.w); h1[6] = f.x; h1[7] = f.y;
        }
        float es0 = 0.f, es1 = 0.f;
#pragma unroll
        for (int c = 0; c < 8; c++) { es0 += h0[c] * a[c]; es1 += h1[c] * a[c]; }
        es0 += __shfl_xor_sync(0xffffffffu, es0, 1);
        es1 += __shfl_xor_sync(0xffffffffu, es1, 1);

        float w0 = 0.f, w1 = 0.f;
        if (v0) {
            float e = es0 + adv;
            e = (e > 0.f) ? e : 0.2f * e;
            w0 = __expf(e);
        }
        if (v1) {
            float e = es1 + adv;
            e = (e > 0.f) ? e : 0.2f * e;
            w1 = __expf(e);
        }
        s += w0 + w1;
#pragma unroll
        for (int c = 0; c < 8; c++) acc[c] += w0 * h0[c] + w1 * h1[c];
    }

    // reduce across pairs only (lanes of a pair hold identical s / half-channel acc)
#pragma unroll
    for (int off = 2; off <= 16; off <<= 1) {
        s += __shfl_xor_sync(0xffffffffu, s, off);
#pragma unroll
        for (int c = 0; c < 8; c++)
            acc[c] += __shfl_xor_sync(0xffffffffu, acc[c], off);
    }

    // epilogue: lane h owns channels h*8..h*8+7; combine partials across the pair
    float inv = 1.0f / (s + 1e-16f);
    int cb = h * 8;
    float s0 = 0.f, s1 = 0.f, d0 = 0.f, d1 = 0.f;
#pragma unroll
    for (int c = 0; c < 8; c++) {
        float hh = fmaxf(acc[c] * inv + __ldg(&bias[cb + c]), 0.f);
        s0 += hh * __ldg(&W2s[(cb + c) * 2 + 0]);
        s1 += hh * __ldg(&W2s[(cb + c) * 2 + 1]);
        d0 += hh * __ldg(&W2d[(cb + c) * 2 + 0]);
        d1 += hh * __ldg(&W2d[(cb + c) * 2 + 1]);
    }
    s0 += __shfl_xor_sync(0xffffffffu, s0, 1);
    s1 += __shfl_xor_sync(0xffffffffu, s1, 1);
    d0 += __shfl_xor_sync(0xffffffffu, d0, 1);
    d1 += __shfl_xor_sync(0xffffffffu, d1, 1);
    if (lane == 0) {
        *(float2*)(hs2_out + (size_t)g * 2) = make_float2(s0, s1);
        ad2_out[g] = d0 * __ldg(&a2d[0]) + d1 * __ldg(&a2d[1]);
    }
}

// ---------------- agg1 user: per-lane gather (R15 exact), G=8, 4 dst/warp ----------
__device__ __forceinline__ void agg1_user(
    int g, int lane,
    const int* __restrict__ cnt, const int* __restrict__ bkt,
    const float* __restrict__ ad_, const uint4* __restrict__ hs,
    const float* __restrict__ avec, const float* __restrict__ bias,
    const float* __restrict__ W2s, const float* __restrict__ W2d,
    const float* __restrict__ a2d,
    float* __restrict__ hs2_out, float* __restrict__ ad2_out) {
    const int G = 8;
    float a[16];
#pragma unroll
    for (int c = 0; c < 16; c++) a[c] = __ldg(&avec[c]);
    float adv = __ldg(&ad_[g]);
    int deg = __ldg(&cnt[g]);
    if (deg > STRIDE_U) deg = STRIDE_U;
    const int* row = bkt + (size_t)g * STRIDE_U;

    float s = 0.f;
    float acc[16];
#pragma unroll
    for (int c = 0; c < 16; c++) acc[c] = 0.f;

    int i = lane;
    int src = (i < deg) ? __ldg(&row[i]) : 0;
    while (i < deg) {
        int inext = i + G;
        int src_next = (inext < deg) ? __ldg(&row[inext]) : 0;
        uint4 v0 = __ldg(&hs[(size_t)src * 2 + 0]);
        uint4 v1 = __ldg(&hs[(size_t)src * 2 + 1]);
        unsigned int w32[8] = {v0.x, v0.y, v0.z, v0.w, v1.x, v1.y, v1.z, v1.w};
        float h[16];
#pragma unroll
        for (int q = 0; q < 8; q++) {
            float2 f = __half22float2(*(__half2*)&w32[q]);
            h[2 * q + 0] = f.x;
            h[2 * q + 1] = f.y;
        }
        float es = 0.f;
#pragma unroll
        for (int c = 0; c < 16; c++) es += h[c] * a[c];
        float e = es + adv;
        e = (e > 0.f) ? e : 0.2f * e;
        float w = __expf(e);
        s += w;
#pragma unroll
        for (int c = 0; c < 16; c++) acc[c] += w * h[c];
        src = src_next;
        i = inext;
    }

#pragma unroll
    for (int off = G / 2; off; off >>= 1) {
        s += __shfl_xor_sync(0xffffffffu, s, off);
#pragma unroll
        for (int c = 0; c < 16; c++)
            acc[c] += __shfl_xor_sync(0xffffffffu, acc[c], off);
    }

    if (lane == 0) {
        float inv = 1.0f / (s + 1e-16f);
        float s0 = 0.f, s1 = 0.f, d0 = 0.f, d1 = 0.f;
#pragma unroll
        for (int c = 0; c < 16; c++) {
            float h = fmaxf(acc[c] * inv + __ldg(&bias[c]), 0.f);
            s0 += h * __ldg(&W2s[c * 2 + 0]);
            s1 += h * __ldg(&W2s[c * 2 + 1]);
            d0 += h * __ldg(&W2d[c * 2 + 0]);
            d1 += h * __ldg(&W2d[c * 2 + 1]);
        }
        *(float2*)(hs2_out + (size_t)g * 2) = make_float2(s0, s1);
        ad2_out[g] = d0 * __ldg(&a2d[0]) + d1 * __ldg(&a2d[1]);
    }
}

__global__ void agg1_all(
    const int* __restrict__ cnt_ub, const int* __restrict__ bkt_ub,
    const float* __restrict__ ad1b, const uint4* __restrict__ hs1u,
    const float* __restrict__ a1ubs, const float* __restrict__ b1ub,
    const float* __restrict__ W2bus, const float* __restrict__ W2ubd,
    const float* __restrict__ a2ubd,
    float* __restrict__ hs2b, float* __restrict__ ad2b,
    const int* __restrict__ cnt_bu, const int* __restrict__ bkt_bu,
    const float* __restrict__ ad1u, const uint4* __restrict__ hs1b,
    const float* __restrict__ a1bus, const float* __restrict__ b1bu,
    const float* __restrict__ W2ubs, const float* __restrict__ W2bud,
    const float* __restrict__ a2bud,
    float* __restrict__ hs2u, float* __restrict__ ad2u) {
    int w = blockIdx.x * (blockDim.x >> 5) + (threadIdx.x >> 5);
    int wl = threadIdx.x & 31;
    if (w < NB) {
        agg1_pair_badge(w, wl, cnt_ub, bkt_ub, ad1b, hs1u, a1ubs, b1ub,
                        W2bus, W2ubd, a2ubd, hs2b, ad2b);
    } else {
        int g = (w - NB) * 4 + (wl >> 3);
        if (g < NU)
            agg1_user(g, wl & 7, cnt_bu, bkt_bu, ad1u, hs1b, a1bus, b1bu,
                      W2ubs, W2bud, a2bud, hs2u, ad2u);
    }
}

// ---------------- layer-2 aggregation (R15 exact; clears cnt after use) ----------
template <int G, int STRIDE>
__device__ __forceinline__ void agg2_grp(int g, int lane,
                                         int* __restrict__ cnt, const int* __restrict__ bkt,
                                         const float* __restrict__ ad_, const float* __restrict__ hs,
                                         const float* __restrict__ avec, const float* __restrict__ bias,
                                         float* __restrict__ out) {
    float a0 = __ldg(&avec[0]), a1 = __ldg(&avec[1]);
    float adv = __ldg(&ad_[g]);
    int deg = cnt[g];
    if (lane == 0) cnt[g] = 0;
    if (deg > STRIDE) deg = STRIDE;
    const int* row = bkt + (size_t)g * STRIDE;

    float s = 0.f, acc0 = 0.f, acc1 = 0.f;
    int i = lane;
    int src = (i < deg) ? __ldg(&row[i]) : 0;
    while (i < deg) {
        int inext = i + G;
        int src_next = (inext < deg) ? __ldg(&row[inext]) : 0;
        float2 v = *(const float2*)(hs + (size_t)src * 2);
        float e = v.x * a0 + v.y * a1 + adv;
        e = (e > 0.f) ? e : 0.2f * e;
        float w = __expf(e);
        s += w;
        acc0 += w * v.x;
        acc1 += w * v.y;
        src = src_next;
        i = inext;
    }
#pragma unroll
    for (int off = G / 2; off; off >>= 1) {
        s    += __shfl_xor_sync(0xffffffffu, s, off);
        acc0 += __shfl_xor_sync(0xffffffffu, acc0, off);
        acc1 += __shfl_xor_sync(0xffffffffu, acc1, off);
    }
    if (lane == 0) {
        float inv = 1.0f / (s + 1e-16f);
        *(float2*)(out + (size_t)g * 2) =
            make_float2(acc0 * inv + __ldg(&bias[0]), acc1 * inv + __ldg(&bias[1]));
    }
}

__global__ void agg2_all(
    int* __restrict__ cnt_ub, const int* __restrict__ bkt_ub,
    const float* __restrict__ ad2b, const float* __restrict__ hs2u,
    const float* __restrict__ a2ubs, const float* __restrict__ b2ub,
    float* __restrict__ out_b,
    int* __restrict__ cnt_bu, const int* __restrict__ bkt_bu,
    const float* __restrict__ ad2u, const float* __restrict__ hs2b,
    const float* __restrict__ a2bus, const float* __restrict__ b2bu,
    float* __restrict__ out_u) {
    int w = blockIdx.x * (blockDim.x >> 5) + (threadIdx.x >> 5);
    int wl = threadIdx.x & 31;
    if (w < NB) {
        agg2_grp<32, STRIDE_B>(w, wl, cnt_ub, bkt_ub, ad2b, hs2u, a2ubs, b2ub, out_b);
    } else {
        int g = (w - NB) * 4 + (wl >> 3);
        if (g < NU)
            agg2_grp<8, STRIDE_U>(g, wl & 7, cnt_bu, bkt_bu, ad2u, hs2b, a2bus, b2bu, out_u);
    }
}

// ---------------- host ----------------
static void* sym_addr(const void* symbol) {
    void* p = nullptr;
    cudaGetSymbolAddress(&p, symbol);
    return p;
}

extern "C" void kernel_launch(void* const* d_in, const int* in_sizes, int n_in,
                              void* d_out, int out_size) {
    const float* x_user  = (const float*)d_in[0];
    const float* x_badge = (const float*)d_in[1];
    const int* ub_src = (const int*)d_in[2];
    const int* ub_dst = (const int*)d_in[3];
    const int* bu_src = (const int*)d_in[4];
    const int* bu_dst = (const int*)d_in[5];

    int iW1ubs = 8, iW1ubd = 9, ia1ubs = 10, ia1ubd = 11, ib1ub = 12;
    int iW1bus, iW1bud, ia1bus, ia1bud, ib1bu;
    int iW2ubs, iW2ubd, ia2ubs, ia2ubd, ib2ub;
    int iW2bus, iW2bud, ia2bus, ia2bud, ib2bu;
    if (in_sizes[13] == 1024) {
        iW1bus = 13; iW1bud = 14; ia1bus = 15; ia1bud = 16; ib1bu = 17;
        iW2ubs = 18; iW2ubd = 19; ia2ubs = 20; ia2ubd = 21; ib2ub = 22;
        iW2bus = 23; iW2bud = 24; ia2bus = 25; ia2bud = 26; ib2bu = 27;
    } else {
        iW2ubs = 13; iW2ubd = 14; ia2ubs = 15; ia2ubd = 16; ib2ub = 17;
        iW1bus = 18; iW1bud = 19; ia1bus = 20; ia1bud = 21; ib1bu = 22;
        iW2bus = 23; iW2bud = 24; ia2bus = 25; ia2bud = 26; ib2bu = 27;
    }
#define FP(i) ((const float*)d_in[i])

    int* cnt     = (int*)sym_addr(g_cnt);
    int* cnt_bu  = cnt;
    int* cnt_ub  = cnt + NU;
    int* bkt_ub  = (int*)sym_addr(g_bkt_ub);
    int* bkt_bu  = (int*)sym_addr(g_bkt_bu);
    uint4* hs1u = (uint4*)sym_addr(g_hs1_u);
    uint4* hs1b = (uint4*)sym_addr(g_hs1_b);
    float* ad1u = (float*)sym_addr(g_ad1_u);
    float* ad1b = (float*)sym_addr(g_ad1_b);
    float* hs2u = (float*)sym_addr(g_hs2_u);
    float* hs2b = (float*)sym_addr(g_hs2_b);
    float* ad2u = (float*)sym_addr(g_ad2_u);
    float* ad2b = (float*)sym_addr(g_ad2_b);

    // ---- bucket build + layer-1 node transforms (fused, interleaved; no memset) ----
    build_node_kernel<<<TOTAL_BLOCKS, 256>>>(
        ub_src, ub_dst, cnt_ub, bkt_ub,
        bu_src, bu_dst, cnt_bu, bkt_bu,
        x_user, x_badge,
        FP(iW1ubs), FP(iW1bud), FP(ia1bud),
        FP(iW1bus), FP(iW1ubd), FP(ia1ubd),
        hs1u, ad1u, hs1b, ad1b);

    // ---- layer 1 aggregation + fused layer-2 node transform (one launch) ----
    {
        long warps = (long)NB + (NU + 3) / 4;
        int blocks = (int)((warps * 32 + 255) / 256);
        agg1_all<<<blocks, 256>>>(
            cnt_ub, bkt_ub, ad1b, hs1u, FP(ia1ubs), FP(ib1ub),
            FP(iW2bus), FP(iW2ubd), FP(ia2ubd), hs2b, ad2b,
            cnt_bu, bkt_bu, ad1u, hs1b, FP(ia1bus), FP(ib1bu),
            FP(iW2ubs), FP(iW2bud), FP(ia2bud), hs2u, ad2u);
    }

    // ---- layer 2 aggregation -> outputs (one launch; clears cnt for next replay) ----
    float* out = (float*)d_out;   // [ou (200000x2) | ob (50000x2)]
    {
        long warps = (long)NB + (NU + 3) / 4;
        int blocks = (int)((warps * 32 + 255) / 256);
        agg2_all<<<blocks, 256>>>(
            cnt_ub, bkt_ub, ad2b, hs2u, FP(ia2ubs), FP(ib2ub), out + (size_t)NU * 2,
            cnt_bu, bkt_bu, ad2u, hs2b, FP(ia2bus), FP(ib2bu), out);
    }
}